// round 1
// baseline (speedup 1.0000x reference)
#include <cuda_runtime.h>
#include <cuda_bf16.h>
#include <cstdint>

// Problem constants
//  B=1024, T=64, E=H=1024, 4H=4096, NCLS=2, VOCAB=50000
//
// Strategy:
//  - Hoist the input GEMM out of the recurrence: Xg[t*B+b][n] = emb[x[b,t]] @ W_ih^T + b_ih + b_hh
//  - Recurrent GEMM per step: gates = Xg + h @ W_hh^T
//  - All GEMMs via mma.sync m16n8k16 bf16 with bf16x3 split (hi+lo) for fp32-class accuracy.
//  - N dimension is gate-interleaved per CTA tile so each thread holds (i,f,g,o) for the
//    same (b,hc) in registers -> fully fused LSTM cell update in the GEMM epilogue.
//  - Pre-gates Xg and the cell state C are stored in MMA *fragment order* so the step
//    kernel's epilogue does perfectly coalesced float4 loads/stores.
//  - Classifier (NCLS=2) folded into the epilogue via shfl-reduce + atomicAdd.

// ------------------------- static device scratch -------------------------
__device__ float          d_Xg[268435456];      // [512 mtile][32 ntile][8 warp][16 mf*8+nf][128] = 1 GiB
__device__ float          d_Cfrag[1048576];     // cell state, fragment order
__device__ __nv_bfloat16  d_h_hi[2][1048576];   // ping-pong hidden state, hi part
__device__ __nv_bfloat16  d_h_lo[2][1048576];   // lo part
__device__ __nv_bfloat16  d_Wih_hi[4194304];
__device__ __nv_bfloat16  d_Wih_lo[4194304];
__device__ __nv_bfloat16  d_Whh_hi[4194304];
__device__ __nv_bfloat16  d_Whh_lo[4194304];
__device__ float          d_logits[131072];     // [T][B][2]

// ------------------------- mma helper -------------------------
__device__ __forceinline__ void mma_bf16(float* d, const uint32_t* a, const uint32_t* b) {
    asm volatile(
        "mma.sync.aligned.m16n8k16.row.col.f32.bf16.bf16.f32 "
        "{%0,%1,%2,%3}, {%4,%5,%6,%7}, {%8,%9}, {%0,%1,%2,%3};\n"
        : "+f"(d[0]), "+f"(d[1]), "+f"(d[2]), "+f"(d[3])
        : "r"(a[0]), "r"(a[1]), "r"(a[2]), "r"(a[3]), "r"(b[0]), "r"(b[1]));
}

// gate-interleaved column mapping: CTA-local col cl in [0,128) -> global n in [0,4096)
// cl = wn*64 + nf*8 + f,  nf = gate*2 + oct,  n = gate*1024 + hc0 + wn*16 + oct*8 + f
__device__ __forceinline__ int n_of(int cl, int hc0) {
    int wn_  = cl >> 6;
    int rem  = cl & 63;
    int nf   = rem >> 3;
    int f    = rem & 7;
    int gate = nf >> 1;
    int oct  = nf & 1;
    return gate * 1024 + hc0 + wn_ * 16 + oct * 8 + f;
}

// one K=32 chunk of the bf16x3 GEMM (both 16-wide sub-steps)
__device__ __forceinline__ void gemm_chunk(
    float acc[2][8][4],
    const __nv_bfloat16 sAh[128][40], const __nv_bfloat16 sAl[128][40],
    const __nv_bfloat16 sBh[128][40], const __nv_bfloat16 sBl[128][40],
    int wm, int wn, int g, int tg)
{
#pragma unroll
    for (int ks = 0; ks < 32; ks += 16) {
        uint32_t ah[2][4], al[2][4], bh[8][2], bl[8][2];
#pragma unroll
        for (int mf = 0; mf < 2; mf++) {
            int R = wm * 32 + mf * 16;
            ah[mf][0] = *(const uint32_t*)&sAh[R + g    ][ks +     2 * tg];
            ah[mf][1] = *(const uint32_t*)&sAh[R + g + 8][ks +     2 * tg];
            ah[mf][2] = *(const uint32_t*)&sAh[R + g    ][ks + 8 + 2 * tg];
            ah[mf][3] = *(const uint32_t*)&sAh[R + g + 8][ks + 8 + 2 * tg];
            al[mf][0] = *(const uint32_t*)&sAl[R + g    ][ks +     2 * tg];
            al[mf][1] = *(const uint32_t*)&sAl[R + g + 8][ks +     2 * tg];
            al[mf][2] = *(const uint32_t*)&sAl[R + g    ][ks + 8 + 2 * tg];
            al[mf][3] = *(const uint32_t*)&sAl[R + g + 8][ks + 8 + 2 * tg];
        }
#pragma unroll
        for (int nf = 0; nf < 8; nf++) {
            int CL = wn * 64 + nf * 8 + g;
            bh[nf][0] = *(const uint32_t*)&sBh[CL][ks +     2 * tg];
            bh[nf][1] = *(const uint32_t*)&sBh[CL][ks + 8 + 2 * tg];
            bl[nf][0] = *(const uint32_t*)&sBl[CL][ks +     2 * tg];
            bl[nf][1] = *(const uint32_t*)&sBl[CL][ks + 8 + 2 * tg];
        }
#pragma unroll
        for (int mf = 0; mf < 2; mf++)
#pragma unroll
            for (int nf = 0; nf < 8; nf++) {
                mma_bf16(acc[mf][nf], ah[mf], bh[nf]);   // hi*hi
                mma_bf16(acc[mf][nf], al[mf], bh[nf]);   // lo*hi
                mma_bf16(acc[mf][nf], ah[mf], bl[nf]);   // hi*lo
            }
    }
}

// ------------------------- init: split weights/h0, layout c0, zero logits -------------------------
__global__ void init_kernel(const float* __restrict__ Wih, const float* __restrict__ Whh,
                            const float* __restrict__ h0,  const float* __restrict__ c0)
{
    int idx = blockIdx.x * 256 + threadIdx.x;
    if (idx < 4194304) {
        float w = Wih[idx];
        __nv_bfloat16 hi = __float2bfloat16(w);
        d_Wih_hi[idx] = hi;
        d_Wih_lo[idx] = __float2bfloat16(w - __bfloat162float(hi));
        w = Whh[idx];
        hi = __float2bfloat16(w);
        d_Whh_hi[idx] = hi;
        d_Whh_lo[idx] = __float2bfloat16(w - __bfloat162float(hi));
    }
    if (idx < 1048576) {
        float v = h0[idx];
        __nv_bfloat16 hi = __float2bfloat16(v);
        d_h_hi[0][idx] = hi;
        d_h_lo[0][idx] = __float2bfloat16(v - __bfloat162float(hi));
        // c0 -> fragment layout
        int b = idx >> 10, hc = idx & 1023;
        int bm = b >> 7, wm = (b >> 5) & 3, mf = (b >> 4) & 1, r = (b >> 3) & 1, g = b & 7;
        int bn = hc >> 5, wn = (hc >> 4) & 1, oct = (hc >> 3) & 1, tg = (hc >> 1) & 3, e = hc & 1;
        int warp = wn * 4 + wm, lane = g * 4 + tg;
        int ci = ((((bm * 32 + bn) * 8 + warp) * 2 + mf) * 32 + lane) * 8 + oct * 4 + r * 2 + e;
        d_Cfrag[ci] = c0[idx];
    }
    if (idx < 131072) d_logits[idx] = 0.0f;
}

// ------------------------- input GEMM: Xg = emb[x] @ W_ih^T + b_ih + b_hh -------------------------
__global__ void __launch_bounds__(256, 2) input_gemm(const int* __restrict__ x,
                                                     const float* __restrict__ emb,
                                                     const float* __restrict__ b_ih,
                                                     const float* __restrict__ b_hh)
{
    __shared__ __nv_bfloat16 sAh[128][40], sAl[128][40], sBh[128][40], sBl[128][40];
    __shared__ int toks[128];

    int tid = threadIdx.x;
    int bn = blockIdx.x;          // n-tile (32 hc cols x 4 gates)
    int bm = blockIdx.y;          // global (t,b)-row tile, 0..511
    int warp = tid >> 5, lane = tid & 31;
    int wm = warp & 3, wn = warp >> 2;
    int g = lane >> 2, tg = lane & 3;
    int hc0 = bn * 32;

    if (tid < 128) {
        int row = bm * 128 + tid;          // row = t*B + b
        int t = row >> 10, b = row & 1023;
        toks[tid] = x[b * 64 + t];
    }
    __syncthreads();

    float acc[2][8][4];
#pragma unroll
    for (int i = 0; i < 2; i++)
#pragma unroll
        for (int j = 0; j < 8; j++)
#pragma unroll
            for (int q = 0; q < 4; q++) acc[i][j][q] = 0.0f;

    for (int kk = 0; kk < 1024; kk += 32) {
        // A: gather embedding rows, split to hi/lo
        for (int i = tid; i < 4096; i += 256) {
            int r = i >> 5, c = i & 31;
            float v = emb[(size_t)toks[r] * 1024 + kk + c];
            __nv_bfloat16 hi = __float2bfloat16(v);
            sAh[r][c] = hi;
            sAl[r][c] = __float2bfloat16(v - __bfloat162float(hi));
        }
        // B: W_ih tile (pre-split), gate-interleaved columns
        for (int i = tid; i < 2048; i += 256) {
            int cl = i >> 4, c2 = i & 15;
            int n = n_of(cl, hc0);
            *(uint32_t*)&sBh[cl][2 * c2] = *(const uint32_t*)&d_Wih_hi[n * 1024 + kk + 2 * c2];
            *(uint32_t*)&sBl[cl][2 * c2] = *(const uint32_t*)&d_Wih_lo[n * 1024 + kk + 2 * c2];
        }
        __syncthreads();
        gemm_chunk(acc, sAh, sAl, sBh, sBl, wm, wn, g, tg);
        __syncthreads();
    }

    // epilogue: add biases, store in fragment order (float4, fully coalesced)
#pragma unroll
    for (int mf = 0; mf < 2; mf++)
#pragma unroll
        for (int nf = 0; nf < 8; nf++) {
            int gate = nf >> 1, oct = nf & 1;
            int hcE0 = hc0 + wn * 16 + oct * 8 + 2 * tg;
            int n0 = gate * 1024 + hcE0;
            float be0 = b_ih[n0] + b_hh[n0];
            float be1 = b_ih[n0 + 1] + b_hh[n0 + 1];
            size_t off = ((((size_t)bm * 32 + bn) * 8 + warp) * 16 + mf * 8 + nf) * 128 + lane * 4;
            float4 v = make_float4(acc[mf][nf][0] + be0, acc[mf][nf][1] + be1,
                                   acc[mf][nf][2] + be0, acc[mf][nf][3] + be1);
            *(float4*)&d_Xg[off] = v;
        }
}

// ------------------------- one recurrent step (fused GEMM + LSTM cell + classifier) -------------------------
__global__ void __launch_bounds__(256, 2) step_kernel(int t,
                                                      const float* __restrict__ Wout,
                                                      const float* __restrict__ b_out,
                                                      float* __restrict__ out)
{
    __shared__ __nv_bfloat16 sAh[128][40], sAl[128][40], sBh[128][40], sBl[128][40];

    int tid = threadIdx.x;
    int bn = blockIdx.x;   // 0..31  (hc tile)
    int bm = blockIdx.y;   // 0..7   (b tile)
    int warp = tid >> 5, lane = tid & 31;
    int wm = warp & 3, wn = warp >> 2;
    int g = lane >> 2, tg = lane & 3;
    int m0 = bm * 128, hc0 = bn * 32;

    // block (0,0): finalize previous step's log-softmax (logits are complete after kernel t-1)
    if (t > 0 && bn == 0 && bm == 0) {
        int tb = (t - 1) << 11;
        for (int i = tid; i < 1024; i += 256) {
            float l0 = d_logits[tb + i * 2 + 0] + b_out[0];
            float l1 = d_logits[tb + i * 2 + 1] + b_out[1];
            float mx = fmaxf(l0, l1);
            float lse = mx + logf(expf(l0 - mx) + expf(l1 - mx));
            out[tb + i * 2 + 0] = l0 - lse;
            out[tb + i * 2 + 1] = l1 - lse;
        }
    }

    const __nv_bfloat16* hHi = d_h_hi[t & 1];
    const __nv_bfloat16* hLo = d_h_lo[t & 1];
    __nv_bfloat16* nHi = d_h_hi[(t + 1) & 1];
    __nv_bfloat16* nLo = d_h_lo[(t + 1) & 1];

    float acc[2][8][4];
#pragma unroll
    for (int i = 0; i < 2; i++)
#pragma unroll
        for (int j = 0; j < 8; j++)
#pragma unroll
            for (int q = 0; q < 4; q++) acc[i][j][q] = 0.0f;

    for (int kk = 0; kk < 1024; kk += 32) {
        for (int i = tid; i < 2048; i += 256) {
            int r = i >> 4, c2 = i & 15;
            *(uint32_t*)&sAh[r][2 * c2] = *(const uint32_t*)&hHi[(m0 + r) * 1024 + kk + 2 * c2];
            *(uint32_t*)&sAl[r][2 * c2] = *(const uint32_t*)&hLo[(m0 + r) * 1024 + kk + 2 * c2];
        }
        for (int i = tid; i < 2048; i += 256) {
            int cl = i >> 4, c2 = i & 15;
            int n = n_of(cl, hc0);
            *(uint32_t*)&sBh[cl][2 * c2] = *(const uint32_t*)&d_Whh_hi[n * 1024 + kk + 2 * c2];
            *(uint32_t*)&sBl[cl][2 * c2] = *(const uint32_t*)&d_Whh_lo[n * 1024 + kk + 2 * c2];
        }
        __syncthreads();
        gemm_chunk(acc, sAh, sAl, sBh, sBl, wm, wn, g, tg);
        __syncthreads();
    }

    // ---------------- fused LSTM epilogue ----------------
    size_t xgbase = ((((size_t)(t * 8 + bm) * 32 + bn) * 8 + warp) * 16) * 128 + lane * 4;
    size_t cbase  = ((((size_t)bm * 32 + bn) * 8 + warp) * 2) * 256 + lane * 8;

    float lsum[2][2][2];
#pragma unroll
    for (int i = 0; i < 2; i++)
#pragma unroll
        for (int j = 0; j < 2; j++) { lsum[i][j][0] = 0.0f; lsum[i][j][1] = 0.0f; }

#pragma unroll
    for (int mf = 0; mf < 2; mf++) {
        float4 CP0 = *(const float4*)&d_Cfrag[cbase + mf * 256 + 0];
        float4 CP1 = *(const float4*)&d_Cfrag[cbase + mf * 256 + 4];
        float cprev[8] = {CP0.x, CP0.y, CP0.z, CP0.w, CP1.x, CP1.y, CP1.z, CP1.w};
        float cnew[8];
#pragma unroll
        for (int oct = 0; oct < 2; oct++) {
            float4 PI = *(const float4*)&d_Xg[xgbase + (size_t)(mf * 8 + 0 + oct) * 128];
            float4 PF = *(const float4*)&d_Xg[xgbase + (size_t)(mf * 8 + 2 + oct) * 128];
            float4 PG = *(const float4*)&d_Xg[xgbase + (size_t)(mf * 8 + 4 + oct) * 128];
            float4 PO = *(const float4*)&d_Xg[xgbase + (size_t)(mf * 8 + 6 + oct) * 128];
            float pri[4] = {PI.x, PI.y, PI.z, PI.w};
            float prf[4] = {PF.x, PF.y, PF.z, PF.w};
            float prg[4] = {PG.x, PG.y, PG.z, PG.w};
            float pro[4] = {PO.x, PO.y, PO.z, PO.w};
#pragma unroll
            for (int q = 0; q < 4; q++) {
                int r = q >> 1, e = q & 1;
                float I = acc[mf][0 + oct][q] + pri[q];
                float F = acc[mf][2 + oct][q] + prf[q];
                float G = acc[mf][4 + oct][q] + prg[q];
                float O = acc[mf][6 + oct][q] + pro[q];
                float si = 1.0f / (1.0f + expf(-I));
                float sf = 1.0f / (1.0f + expf(-F));
                float so = 1.0f / (1.0f + expf(-O));
                float c2 = sf * cprev[oct * 4 + q] + si * tanhf(G);
                float h2 = so * tanhf(c2);
                cnew[oct * 4 + q] = c2;
                int b  = m0 + wm * 32 + mf * 16 + r * 8 + g;
                int hc = hc0 + wn * 16 + oct * 8 + 2 * tg + e;
                __nv_bfloat16 hi = __float2bfloat16(h2);
                nHi[b * 1024 + hc] = hi;
                nLo[b * 1024 + hc] = __float2bfloat16(h2 - __bfloat162float(hi));
                lsum[mf][r][0] += c2 * Wout[hc];
                lsum[mf][r][1] += c2 * Wout[1024 + hc];
            }
        }
        *(float4*)&d_Cfrag[cbase + mf * 256 + 0] = make_float4(cnew[0], cnew[1], cnew[2], cnew[3]);
        *(float4*)&d_Cfrag[cbase + mf * 256 + 4] = make_float4(cnew[4], cnew[5], cnew[6], cnew[7]);
    }

    // reduce partial logits across the 4 tg-lanes (same b), then one atomic per (b, cls)
#pragma unroll
    for (int mf = 0; mf < 2; mf++)
#pragma unroll
        for (int r = 0; r < 2; r++)
#pragma unroll
            for (int cls = 0; cls < 2; cls++) {
                float v = lsum[mf][r][cls];
                v += __shfl_xor_sync(0xffffffffu, v, 1);
                v += __shfl_xor_sync(0xffffffffu, v, 2);
                if (tg == 0) {
                    int b = m0 + wm * 32 + mf * 16 + r * 8 + g;
                    atomicAdd(&d_logits[(t << 11) + b * 2 + cls], v);
                }
            }
}

// ------------------------- finalize t=63 + out_final -------------------------
__global__ void final_kernel(const float* __restrict__ b_out, float* __restrict__ out)
{
    int i = blockIdx.x * 256 + threadIdx.x;
    if (i < 1024) {
        int tb = 63 << 11;
        float l0 = d_logits[tb + i * 2 + 0] + b_out[0];
        float l1 = d_logits[tb + i * 2 + 1] + b_out[1];
        float mx = fmaxf(l0, l1);
        float lse = mx + logf(expf(l0 - mx) + expf(l1 - mx));
        out[tb + i * 2 + 0] = l0 - lse;
        out[tb + i * 2 + 1] = l1 - lse;
        out[131072 + i * 2 + 0] = l0;   // out_final = c_T @ W_out^T + b_out (raw)
        out[131072 + i * 2 + 1] = l1;
    }
}

// ------------------------- launch -------------------------
extern "C" void kernel_launch(void* const* d_in, const int* in_sizes, int n_in,
                              void* d_out, int out_size)
{
    (void)in_sizes; (void)n_in; (void)out_size;
    const int*   x    = (const int*)d_in[0];
    const float* emb  = (const float*)d_in[1];
    const float* Wih  = (const float*)d_in[2];
    const float* Whh  = (const float*)d_in[3];
    const float* bih  = (const float*)d_in[4];
    const float* bhh  = (const float*)d_in[5];
    const float* Wout = (const float*)d_in[6];
    const float* bout = (const float*)d_in[7];
    const float* h0   = (const float*)d_in[8];
    const float* c0   = (const float*)d_in[9];
    float* out = (float*)d_out;

    init_kernel<<<16384, 256>>>(Wih, Whh, h0, c0);
    input_gemm<<<dim3(32, 512), 256>>>(x, emb, bih, bhh);
    for (int t = 0; t < 64; t++)
        step_kernel<<<dim3(32, 8), 256>>>(t, Wout, bout, out);
    final_kernel<<<4, 256>>>(bout, out);
}

// round 3
// speedup vs baseline: 1.9150x; 1.9150x over previous
#include <cuda_runtime.h>
#include <cuda_bf16.h>
#include <cstdint>

// B=1024, T=64, E=H=1024, 4H=4096, NCLS=2, VOCAB=50000
// mma.sync (HMMA) bf16x3 engine, cp.async double-buffered, CTA tile 128x128,
// warp tile 32x64, gate-interleaved N so the LSTM cell update fuses in-register.

#define CTRL  1024
#define STAGE 40960                    // Ah 10240 | Al 10240 | Bh 10240 | Bl 10240
#define SMEM_BYTES (CTRL + 2 * STAGE)  // 82944

// ------------------------- static device scratch -------------------------
__device__ float          d_Xg[268435456];      // pre-gates, MMA fragment order
__device__ float          d_Cfrag[1048576];     // cell state, fragment order
__device__ __nv_bfloat16  d_h_hi[2][1048576];
__device__ __nv_bfloat16  d_h_lo[2][1048576];
__device__ __nv_bfloat16  d_Wih_hi[4194304];
__device__ __nv_bfloat16  d_Wih_lo[4194304];
__device__ __nv_bfloat16  d_Whh_hi[4194304];
__device__ __nv_bfloat16  d_Whh_lo[4194304];
__device__ __nv_bfloat16  d_emb_hi[51200000];
__device__ __nv_bfloat16  d_emb_lo[51200000];
__device__ float          d_logits[131072];     // [T][B][2]

// ------------------------- helpers -------------------------
__device__ __forceinline__ uint32_t smem_u32(const void* p) {
    uint32_t a;
    asm("{ .reg .u64 t; cvta.to.shared.u64 t, %1; cvt.u32.u64 %0, t; }" : "=r"(a) : "l"(p));
    return a;
}

#define CP16(dst, src) \
    asm volatile("cp.async.cg.shared.global [%0], [%1], 16;" :: "r"(dst), "l"(src) : "memory")
#define CP_COMMIT() asm volatile("cp.async.commit_group;" ::: "memory")
#define CP_WAIT1()  asm volatile("cp.async.wait_group 1;" ::: "memory")

__device__ __forceinline__ void mma_bf16(float* d, const uint32_t* a, const uint32_t* b) {
    asm volatile(
        "mma.sync.aligned.m16n8k16.row.col.f32.bf16.bf16.f32 "
        "{%0,%1,%2,%3}, {%4,%5,%6,%7}, {%8,%9}, {%0,%1,%2,%3};\n"
        : "+f"(d[0]), "+f"(d[1]), "+f"(d[2]), "+f"(d[3])
        : "r"(a[0]), "r"(a[1]), "r"(a[2]), "r"(a[3]), "r"(b[0]), "r"(b[1]));
}

// gate-interleaved column mapping: CTA-local col cl in [0,128) -> global n in [0,4096)
__device__ __forceinline__ int n_of(int cl, int hc0) {
    int wn_  = cl >> 6;
    int rem  = cl & 63;
    int nf   = rem >> 3;
    int f    = rem & 7;
    int gate = nf >> 1;
    int oct  = nf & 1;
    return gate * 1024 + hc0 + wn_ * 16 + oct * 8 + f;
}

typedef const __nv_bfloat16 (*TileP)[40];

// one K=32 chunk of the bf16x3 GEMM
__device__ __forceinline__ void gemm_chunk(
    float acc[2][8][4], TileP sAh, TileP sAl, TileP sBh, TileP sBl,
    int wm, int wn, int g, int tg)
{
#pragma unroll
    for (int ks = 0; ks < 32; ks += 16) {
        uint32_t ah[2][4], al[2][4], bh[8][2], bl[8][2];
#pragma unroll
        for (int mf = 0; mf < 2; mf++) {
            int R = wm * 32 + mf * 16;
            ah[mf][0] = *(const uint32_t*)&sAh[R + g    ][ks +     2 * tg];
            ah[mf][1] = *(const uint32_t*)&sAh[R + g + 8][ks +     2 * tg];
            ah[mf][2] = *(const uint32_t*)&sAh[R + g    ][ks + 8 + 2 * tg];
            ah[mf][3] = *(const uint32_t*)&sAh[R + g + 8][ks + 8 + 2 * tg];
            al[mf][0] = *(const uint32_t*)&sAl[R + g    ][ks +     2 * tg];
            al[mf][1] = *(const uint32_t*)&sAl[R + g + 8][ks +     2 * tg];
            al[mf][2] = *(const uint32_t*)&sAl[R + g    ][ks + 8 + 2 * tg];
            al[mf][3] = *(const uint32_t*)&sAl[R + g + 8][ks + 8 + 2 * tg];
        }
#pragma unroll
        for (int nf = 0; nf < 8; nf++) {
            int CL = wn * 64 + nf * 8 + g;
            bh[nf][0] = *(const uint32_t*)&sBh[CL][ks +     2 * tg];
            bh[nf][1] = *(const uint32_t*)&sBh[CL][ks + 8 + 2 * tg];
            bl[nf][0] = *(const uint32_t*)&sBl[CL][ks +     2 * tg];
            bl[nf][1] = *(const uint32_t*)&sBl[CL][ks + 8 + 2 * tg];
        }
#pragma unroll
        for (int mf = 0; mf < 2; mf++)
#pragma unroll
            for (int nf = 0; nf < 8; nf++) {
                mma_bf16(acc[mf][nf], ah[mf], bh[nf]);
                mma_bf16(acc[mf][nf], al[mf], bh[nf]);
                mma_bf16(acc[mf][nf], ah[mf], bl[nf]);
            }
    }
}

// ------------------------- init: split weights/emb/h0, layout c0 -------------------------
__global__ void init_kernel(const float* __restrict__ Wih, const float* __restrict__ Whh,
                            const float* __restrict__ emb,
                            const float* __restrict__ h0,  const float* __restrict__ c0)
{
    int idx = blockIdx.x * 256 + threadIdx.x;
    if (idx < 4194304) {
        float w = Wih[idx];
        __nv_bfloat16 hi = __float2bfloat16(w);
        d_Wih_hi[idx] = hi;
        d_Wih_lo[idx] = __float2bfloat16(w - __bfloat162float(hi));
        w = Whh[idx];
        hi = __float2bfloat16(w);
        d_Whh_hi[idx] = hi;
        d_Whh_lo[idx] = __float2bfloat16(w - __bfloat162float(hi));
    }
    for (long i = idx; i < 51200000L; i += 4194304L) {
        float v = emb[i];
        __nv_bfloat16 hi = __float2bfloat16(v);
        d_emb_hi[i] = hi;
        d_emb_lo[i] = __float2bfloat16(v - __bfloat162float(hi));
    }
    if (idx < 1048576) {
        float v = h0[idx];
        __nv_bfloat16 hi = __float2bfloat16(v);
        d_h_hi[0][idx] = hi;
        d_h_lo[0][idx] = __float2bfloat16(v - __bfloat162float(hi));
        int b = idx >> 10, hc = idx & 1023;
        int bm = b >> 7, wm = (b >> 5) & 3, mf = (b >> 4) & 1, r = (b >> 3) & 1, g = b & 7;
        int bn = hc >> 5, wn = (hc >> 4) & 1, oct = (hc >> 3) & 1, tg = (hc >> 1) & 3, e = hc & 1;
        int warp = wn * 4 + wm, lane = g * 4 + tg;
        int ci = ((((bm * 32 + bn) * 8 + warp) * 2 + mf) * 32 + lane) * 8 + oct * 4 + r * 2 + e;
        d_Cfrag[ci] = c0[idx];
    }
    if (idx < 131072) d_logits[idx] = 0.0f;
}

// ------------------------- input GEMM: Xg = emb[x] @ W_ih^T + (b_ih + b_hh) -------------------------
__global__ void __launch_bounds__(256, 2) input_gemm(const int* __restrict__ x,
                                                     const float* __restrict__ b_ih,
                                                     const float* __restrict__ b_hh)
{
    extern __shared__ char smem[];
    uint32_t sb = smem_u32(smem);
    int tid = threadIdx.x;
    int bn = blockIdx.x, bm = blockIdx.y;
    int warp = tid >> 5, lane = tid & 31;
    int wm = warp & 3, wn = warp >> 2;
    int g = lane >> 2, tg = lane & 3;
    int hc0 = bn * 32;

    int* toks = (int*)smem;
    if (tid < 128) {
        int row = bm * 128 + tid;          // row = t*B + b
        toks[tid] = x[(row & 1023) * 64 + (row >> 10)];
    }
    __syncthreads();

    // per-thread fill constants (each thread copies 8x16B per chunk)
    int r = tid >> 2, c = tid & 3;
    uint32_t offA0 = (uint32_t)(r * 80 + c * 16);
    uint32_t offA1 = (uint32_t)((r + 64) * 80 + c * 16);
    size_t aoff0 = (size_t)toks[r]      * 1024 + c * 8;
    size_t aoff1 = (size_t)toks[r + 64] * 1024 + c * 8;
    size_t boff0 = (size_t)n_of(r,      hc0) * 1024 + c * 8;
    size_t boff1 = (size_t)n_of(r + 64, hc0) * 1024 + c * 8;

    float acc[2][8][4];
#pragma unroll
    for (int i = 0; i < 2; i++)
#pragma unroll
        for (int j = 0; j < 8; j++)
#pragma unroll
            for (int q = 0; q < 4; q++) acc[i][j][q] = 0.0f;

    // prefetch chunk 0
    {
        uint32_t st = sb + CTRL;
        CP16(st +         offA0, d_emb_hi + aoff0);
        CP16(st + 10240 + offA0, d_emb_lo + aoff0);
        CP16(st +         offA1, d_emb_hi + aoff1);
        CP16(st + 10240 + offA1, d_emb_lo + aoff1);
        CP16(st + 20480 + offA0, d_Wih_hi + boff0);
        CP16(st + 30720 + offA0, d_Wih_lo + boff0);
        CP16(st + 20480 + offA1, d_Wih_hi + boff1);
        CP16(st + 30720 + offA1, d_Wih_lo + boff1);
    }
    CP_COMMIT();

    for (int kt = 0; kt < 32; kt++) {
        if (kt + 1 < 32) {
            int k0 = (kt + 1) * 32;
            uint32_t st = sb + CTRL + ((kt + 1) & 1) * STAGE;
            CP16(st +         offA0, d_emb_hi + aoff0 + k0);
            CP16(st + 10240 + offA0, d_emb_lo + aoff0 + k0);
            CP16(st +         offA1, d_emb_hi + aoff1 + k0);
            CP16(st + 10240 + offA1, d_emb_lo + aoff1 + k0);
            CP16(st + 20480 + offA0, d_Wih_hi + boff0 + k0);
            CP16(st + 30720 + offA0, d_Wih_lo + boff0 + k0);
            CP16(st + 20480 + offA1, d_Wih_hi + boff1 + k0);
            CP16(st + 30720 + offA1, d_Wih_lo + boff1 + k0);
        }
        CP_COMMIT();
        CP_WAIT1();
        __syncthreads();
        char* s0 = smem + CTRL + (kt & 1) * STAGE;
        gemm_chunk(acc, (TileP)s0, (TileP)(s0 + 10240), (TileP)(s0 + 20480), (TileP)(s0 + 30720),
                   wm, wn, g, tg);
        __syncthreads();
    }

    // epilogue: add biases, store in fragment order
#pragma unroll
    for (int mf = 0; mf < 2; mf++)
#pragma unroll
        for (int nf = 0; nf < 8; nf++) {
            int gate = nf >> 1, oct = nf & 1;
            int hcE0 = hc0 + wn * 16 + oct * 8 + 2 * tg;
            int n0 = gate * 1024 + hcE0;
            float be0 = b_ih[n0] + b_hh[n0];
            float be1 = b_ih[n0 + 1] + b_hh[n0 + 1];
            size_t off = ((((size_t)bm * 32 + bn) * 8 + warp) * 16 + mf * 8 + nf) * 128 + lane * 4;
            float4 v = make_float4(acc[mf][nf][0] + be0, acc[mf][nf][1] + be1,
                                   acc[mf][nf][2] + be0, acc[mf][nf][3] + be1);
            *(float4*)&d_Xg[off] = v;
        }
}

// NOTE on K loop count above: K=1024 with chunk 32 -> 32 chunks.

// ------------------------- one recurrent step -------------------------
__global__ void __launch_bounds__(256, 2) step_kernel(int t,
                                                      const float* __restrict__ Wout,
                                                      const float* __restrict__ b_out,
                                                      float* __restrict__ out)
{
    extern __shared__ char smem[];
    uint32_t sb = smem_u32(smem);
    int tid = threadIdx.x;
    int bn = blockIdx.x, bm = blockIdx.y;
    int warp = tid >> 5, lane = tid & 31;
    int wm = warp & 3, wn = warp >> 2;
    int g = lane >> 2, tg = lane & 3;
    int m0 = bm * 128, hc0 = bn * 32;

    // finalize previous step's log-softmax
    if (t > 0 && bn == 0 && bm == 0) {
        int tb = (t - 1) << 11;
        for (int i = tid; i < 1024; i += 256) {
            float l0 = d_logits[tb + i * 2 + 0] + b_out[0];
            float l1 = d_logits[tb + i * 2 + 1] + b_out[1];
            float mx = fmaxf(l0, l1);
            float lse = mx + logf(expf(l0 - mx) + expf(l1 - mx));
            out[tb + i * 2 + 0] = l0 - lse;
            out[tb + i * 2 + 1] = l1 - lse;
        }
    }

    const __nv_bfloat16* hHi = d_h_hi[t & 1];
    const __nv_bfloat16* hLo = d_h_lo[t & 1];
    __nv_bfloat16* nHi = d_h_hi[(t + 1) & 1];
    __nv_bfloat16* nLo = d_h_lo[(t + 1) & 1];

    int r = tid >> 2, c = tid & 3;
    uint32_t offA0 = (uint32_t)(r * 80 + c * 16);
    uint32_t offA1 = (uint32_t)((r + 64) * 80 + c * 16);
    size_t aoff0 = (size_t)(m0 + r)      * 1024 + c * 8;
    size_t aoff1 = (size_t)(m0 + r + 64) * 1024 + c * 8;
    size_t boff0 = (size_t)n_of(r,      hc0) * 1024 + c * 8;
    size_t boff1 = (size_t)n_of(r + 64, hc0) * 1024 + c * 8;

    float acc[2][8][4];
#pragma unroll
    for (int i = 0; i < 2; i++)
#pragma unroll
        for (int j = 0; j < 8; j++)
#pragma unroll
            for (int q = 0; q < 4; q++) acc[i][j][q] = 0.0f;

    {
        uint32_t st = sb + CTRL;
        CP16(st +         offA0, hHi + aoff0);
        CP16(st + 10240 + offA0, hLo + aoff0);
        CP16(st +         offA1, hHi + aoff1);
        CP16(st + 10240 + offA1, hLo + aoff1);
        CP16(st + 20480 + offA0, d_Whh_hi + boff0);
        CP16(st + 30720 + offA0, d_Whh_lo + boff0);
        CP16(st + 20480 + offA1, d_Whh_hi + boff1);
        CP16(st + 30720 + offA1, d_Whh_lo + boff1);
    }
    CP_COMMIT();

    for (int kt = 0; kt < 32; kt++) {
        if (kt + 1 < 32) {
            int k0 = (kt + 1) * 32;
            uint32_t st = sb + CTRL + ((kt + 1) & 1) * STAGE;
            CP16(st +         offA0, hHi + aoff0 + k0);
            CP16(st + 10240 + offA0, hLo + aoff0 + k0);
            CP16(st +         offA1, hHi + aoff1 + k0);
            CP16(st + 10240 + offA1, hLo + aoff1 + k0);
            CP16(st + 20480 + offA0, d_Whh_hi + boff0 + k0);
            CP16(st + 30720 + offA0, d_Whh_lo + boff0 + k0);
            CP16(st + 20480 + offA1, d_Whh_hi + boff1 + k0);
            CP16(st + 30720 + offA1, d_Whh_lo + boff1 + k0);
        }
        CP_COMMIT();
        CP_WAIT1();
        __syncthreads();
        char* s0 = smem + CTRL + (kt & 1) * STAGE;
        gemm_chunk(acc, (TileP)s0, (TileP)(s0 + 10240), (TileP)(s0 + 20480), (TileP)(s0 + 30720),
                   wm, wn, g, tg);
        __syncthreads();
    }

    // ---------------- fused LSTM epilogue ----------------
    size_t xgbase = ((((size_t)(t * 8 + bm) * 32 + bn) * 8 + warp) * 16) * 128 + lane * 4;
    size_t cbase  = ((((size_t)bm * 32 + bn) * 8 + warp) * 2) * 256 + lane * 8;

    float lsum[2][2][2];
#pragma unroll
    for (int i = 0; i < 2; i++)
#pragma unroll
        for (int j = 0; j < 2; j++) { lsum[i][j][0] = 0.0f; lsum[i][j][1] = 0.0f; }

#pragma unroll
    for (int mf = 0; mf < 2; mf++) {
        float4 CP0 = *(const float4*)&d_Cfrag[cbase + mf * 256 + 0];
        float4 CP1 = *(const float4*)&d_Cfrag[cbase + mf * 256 + 4];
        float cprev[8] = {CP0.x, CP0.y, CP0.z, CP0.w, CP1.x, CP1.y, CP1.z, CP1.w};
        float cnew[8];
#pragma unroll
        for (int oct = 0; oct < 2; oct++) {
            float4 PI = *(const float4*)&d_Xg[xgbase + (size_t)(mf * 8 + 0 + oct) * 128];
            float4 PF = *(const float4*)&d_Xg[xgbase + (size_t)(mf * 8 + 2 + oct) * 128];
            float4 PG = *(const float4*)&d_Xg[xgbase + (size_t)(mf * 8 + 4 + oct) * 128];
            float4 PO = *(const float4*)&d_Xg[xgbase + (size_t)(mf * 8 + 6 + oct) * 128];
            float pri[4] = {PI.x, PI.y, PI.z, PI.w};
            float prf[4] = {PF.x, PF.y, PF.z, PF.w};
            float prg[4] = {PG.x, PG.y, PG.z, PG.w};
            float pro[4] = {PO.x, PO.y, PO.z, PO.w};
#pragma unroll
            for (int q = 0; q < 4; q++) {
                int rr = q >> 1, e = q & 1;
                float I = acc[mf][0 + oct][q] + pri[q];
                float F = acc[mf][2 + oct][q] + prf[q];
                float G = acc[mf][4 + oct][q] + prg[q];
                float O = acc[mf][6 + oct][q] + pro[q];
                float si = 1.0f / (1.0f + expf(-I));
                float sf = 1.0f / (1.0f + expf(-F));
                float so = 1.0f / (1.0f + expf(-O));
                float c2 = sf * cprev[oct * 4 + q] + si * tanhf(G);
                float h2 = so * tanhf(c2);
                cnew[oct * 4 + q] = c2;
                int b  = m0 + wm * 32 + mf * 16 + rr * 8 + g;
                int hc = hc0 + wn * 16 + oct * 8 + 2 * tg + e;
                __nv_bfloat16 hi = __float2bfloat16(h2);
                nHi[b * 1024 + hc] = hi;
                nLo[b * 1024 + hc] = __float2bfloat16(h2 - __bfloat162float(hi));
                lsum[mf][rr][0] += c2 * Wout[hc];
                lsum[mf][rr][1] += c2 * Wout[1024 + hc];
            }
        }
        *(float4*)&d_Cfrag[cbase + mf * 256 + 0] = make_float4(cnew[0], cnew[1], cnew[2], cnew[3]);
        *(float4*)&d_Cfrag[cbase + mf * 256 + 4] = make_float4(cnew[4], cnew[5], cnew[6], cnew[7]);
    }

#pragma unroll
    for (int mf = 0; mf < 2; mf++)
#pragma unroll
        for (int rr = 0; rr < 2; rr++)
#pragma unroll
            for (int cls = 0; cls < 2; cls++) {
                float v = lsum[mf][rr][cls];
                v += __shfl_xor_sync(0xffffffffu, v, 1);
                v += __shfl_xor_sync(0xffffffffu, v, 2);
                if (tg == 0) {
                    int b = m0 + wm * 32 + mf * 16 + rr * 8 + g;
                    atomicAdd(&d_logits[(t << 11) + b * 2 + cls], v);
                }
            }
}

// ------------------------- finalize t=63 + out_final -------------------------
__global__ void final_kernel(const float* __restrict__ b_out, float* __restrict__ out)
{
    int i = blockIdx.x * 256 + threadIdx.x;
    if (i < 1024) {
        int tb = 63 << 11;
        float l0 = d_logits[tb + i * 2 + 0] + b_out[0];
        float l1 = d_logits[tb + i * 2 + 1] + b_out[1];
        float mx = fmaxf(l0, l1);
        float lse = mx + logf(expf(l0 - mx) + expf(l1 - mx));
        out[tb + i * 2 + 0] = l0 - lse;
        out[tb + i * 2 + 1] = l1 - lse;
        out[131072 + i * 2 + 0] = l0;
        out[131072 + i * 2 + 1] = l1;
    }
}

// ------------------------- launch -------------------------
extern "C" void kernel_launch(void* const* d_in, const int* in_sizes, int n_in,
                              void* d_out, int out_size)
{
    (void)in_sizes; (void)n_in; (void)out_size;
    const int*   x    = (const int*)d_in[0];
    const float* emb  = (const float*)d_in[1];
    const float* Wih  = (const float*)d_in[2];
    const float* Whh  = (const float*)d_in[3];
    const float* bih  = (const float*)d_in[4];
    const float* bhh  = (const float*)d_in[5];
    const float* Wout = (const float*)d_in[6];
    const float* bout = (const float*)d_in[7];
    const float* h0   = (const float*)d_in[8];
    const float* c0   = (const float*)d_in[9];
    float* out = (float*)d_out;

    cudaFuncSetAttribute(input_gemm, cudaFuncAttributeMaxDynamicSharedMemorySize, SMEM_BYTES);
    cudaFuncSetAttribute(step_kernel, cudaFuncAttributeMaxDynamicSharedMemorySize, SMEM_BYTES);

    init_kernel<<<16384, 256>>>(Wih, Whh, emb, h0, c0);
    input_gemm<<<dim3(32, 512), 256, SMEM_BYTES>>>(x, bih, bhh);
    for (int t = 0; t < 64; t++)
        step_kernel<<<dim3(32, 8), 256, SMEM_BYTES>>>(t, Wout, bout, out);
    final_kernel<<<4, 256>>>(bout, out);
}

// round 4
// speedup vs baseline: 2.0261x; 1.0580x over previous
#include <cuda_runtime.h>
#include <cuda_bf16.h>
#include <cstdint>

// B=1024, T=64, E=H=1024, 4H=4096, NCLS=2, VOCAB=50000
// mma.sync (HMMA) bf16x3 engine, cp.async double-buffered, ldmatrix fragment loads.
// CTA tile 128x128, warp tile 32x64, gate-interleaved N -> fused LSTM epilogue.

#define CTRL  1024
#define STAGE 40960                    // Ah 10240 | Al 10240 | Bh 10240 | Bl 10240
#define SMEM_BYTES (CTRL + 2 * STAGE)  // 82944

// ------------------------- static device scratch -------------------------
__device__ float          d_Xg[268435456];      // pre-gates, MMA fragment order
__device__ float          d_Cfrag[1048576];     // cell state, fragment order
__device__ __nv_bfloat16  d_h_hi[2][1048576];
__device__ __nv_bfloat16  d_h_lo[2][1048576];
__device__ __nv_bfloat16  d_Wih_hi[4194304];
__device__ __nv_bfloat16  d_Wih_lo[4194304];
__device__ __nv_bfloat16  d_Whh_hi[4194304];
__device__ __nv_bfloat16  d_Whh_lo[4194304];
__device__ __nv_bfloat16  d_emb_hi[51200000];
__device__ __nv_bfloat16  d_emb_lo[51200000];
__device__ float          d_logits[131072];     // [T][B][2]

// ------------------------- helpers -------------------------
__device__ __forceinline__ uint32_t smem_u32(const void* p) {
    uint32_t a;
    asm("{ .reg .u64 t; cvta.to.shared.u64 t, %1; cvt.u32.u64 %0, t; }" : "=r"(a) : "l"(p));
    return a;
}

#define CP16(dst, src) \
    asm volatile("cp.async.cg.shared.global [%0], [%1], 16;" :: "r"(dst), "l"(src) : "memory")
#define CP_COMMIT() asm volatile("cp.async.commit_group;" ::: "memory")
#define CP_WAIT1()  asm volatile("cp.async.wait_group 1;" ::: "memory")

#define LDSM4(r0, r1, r2, r3, addr) \
    asm volatile("ldmatrix.sync.aligned.m8n8.x4.shared.b16 {%0,%1,%2,%3}, [%4];" \
        : "=r"(r0), "=r"(r1), "=r"(r2), "=r"(r3) : "r"(addr))

__device__ __forceinline__ void mma_bf16(float* d, const uint32_t* a, const uint32_t* b) {
    asm volatile(
        "mma.sync.aligned.m16n8k16.row.col.f32.bf16.bf16.f32 "
        "{%0,%1,%2,%3}, {%4,%5,%6,%7}, {%8,%9}, {%0,%1,%2,%3};\n"
        : "+f"(d[0]), "+f"(d[1]), "+f"(d[2]), "+f"(d[3])
        : "r"(a[0]), "r"(a[1]), "r"(a[2]), "r"(a[3]), "r"(b[0]), "r"(b[1]));
}

// gate-interleaved column mapping: CTA-local col cl in [0,128) -> global n in [0,4096)
__device__ __forceinline__ int n_of(int cl, int hc0) {
    int wn_  = cl >> 6;
    int rem  = cl & 63;
    int nf   = rem >> 3;
    int f    = rem & 7;
    int gate = nf >> 1;
    int oct  = nf & 1;
    return gate * 1024 + hc0 + wn_ * 16 + oct * 8 + f;
}

// one K=32 chunk of the bf16x3 GEMM, fragments via ldmatrix.
// aH/aL/bH/bL: per-lane smem addresses into the 4 stage regions.
//  aH = base + (wm*32 + (lane&15))*80 + (lane>>4)*16
//  bH = base + (wn*64 + ((lane>>4)<<3) + (lane&7))*80 + ((lane>>3)&1)*16
// LDSM x4 at A yields the m16k16 fragment {a0,a1,a2,a3}; at B yields
// {b[nf][klo], b[nf][khi], b[nf+1][klo], b[nf+1][khi]} for an nf-pair.
__device__ __forceinline__ void gemm_chunk(
    float acc[2][8][4], uint32_t aH, uint32_t aL, uint32_t bH, uint32_t bL)
{
#pragma unroll
    for (int ks = 0; ks < 32; ks += 16) {
        uint32_t ah[2][4], al[2][4];
        LDSM4(ah[0][0], ah[0][1], ah[0][2], ah[0][3], aH + ks * 2);
        LDSM4(ah[1][0], ah[1][1], ah[1][2], ah[1][3], aH + 1280 + ks * 2);
        LDSM4(al[0][0], al[0][1], al[0][2], al[0][3], aL + ks * 2);
        LDSM4(al[1][0], al[1][1], al[1][2], al[1][3], aL + 1280 + ks * 2);
#pragma unroll
        for (int nfp = 0; nfp < 4; nfp++) {
            uint32_t bh[4], bl[4];
            LDSM4(bh[0], bh[1], bh[2], bh[3], bH + nfp * 1280 + ks * 2);
            LDSM4(bl[0], bl[1], bl[2], bl[3], bL + nfp * 1280 + ks * 2);
#pragma unroll
            for (int mf = 0; mf < 2; mf++) {
                mma_bf16(acc[mf][2 * nfp    ], ah[mf], bh    );
                mma_bf16(acc[mf][2 * nfp    ], al[mf], bh    );
                mma_bf16(acc[mf][2 * nfp    ], ah[mf], bl    );
                mma_bf16(acc[mf][2 * nfp + 1], ah[mf], bh + 2);
                mma_bf16(acc[mf][2 * nfp + 1], al[mf], bh + 2);
                mma_bf16(acc[mf][2 * nfp + 1], ah[mf], bl + 2);
            }
        }
    }
}

// ------------------------- init: split weights/emb/h0, layout c0 -------------------------
__global__ void init_kernel(const float* __restrict__ Wih, const float* __restrict__ Whh,
                            const float* __restrict__ emb,
                            const float* __restrict__ h0,  const float* __restrict__ c0)
{
    int idx = blockIdx.x * 256 + threadIdx.x;
    if (idx < 4194304) {
        float w = Wih[idx];
        __nv_bfloat16 hi = __float2bfloat16(w);
        d_Wih_hi[idx] = hi;
        d_Wih_lo[idx] = __float2bfloat16(w - __bfloat162float(hi));
        w = Whh[idx];
        hi = __float2bfloat16(w);
        d_Whh_hi[idx] = hi;
        d_Whh_lo[idx] = __float2bfloat16(w - __bfloat162float(hi));
    }
    for (long i4 = idx; i4 < 12800000L; i4 += 4194304L) {
        float4 v = *(const float4*)&emb[i4 * 4];
        __nv_bfloat16 h0b = __float2bfloat16(v.x), h1b = __float2bfloat16(v.y);
        __nv_bfloat16 h2b = __float2bfloat16(v.z), h3b = __float2bfloat16(v.w);
        union { __nv_bfloat162 b2[2]; uint2 u; } Uh, Ul;
        Uh.b2[0] = __nv_bfloat162(h0b, h1b); Uh.b2[1] = __nv_bfloat162(h2b, h3b);
        Ul.b2[0] = __nv_bfloat162(__float2bfloat16(v.x - __bfloat162float(h0b)),
                                  __float2bfloat16(v.y - __bfloat162float(h1b)));
        Ul.b2[1] = __nv_bfloat162(__float2bfloat16(v.z - __bfloat162float(h2b)),
                                  __float2bfloat16(v.w - __bfloat162float(h3b)));
        *(uint2*)&d_emb_hi[i4 * 4] = Uh.u;
        *(uint2*)&d_emb_lo[i4 * 4] = Ul.u;
    }
    if (idx < 1048576) {
        float v = h0[idx];
        __nv_bfloat16 hi = __float2bfloat16(v);
        d_h_hi[0][idx] = hi;
        d_h_lo[0][idx] = __float2bfloat16(v - __bfloat162float(hi));
        int b = idx >> 10, hc = idx & 1023;
        int bm = b >> 7, wm = (b >> 5) & 3, mf = (b >> 4) & 1, r = (b >> 3) & 1, g = b & 7;
        int bn = hc >> 5, wn = (hc >> 4) & 1, oct = (hc >> 3) & 1, tg = (hc >> 1) & 3, e = hc & 1;
        int warp = wn * 4 + wm, lane = g * 4 + tg;
        int ci = ((((bm * 32 + bn) * 8 + warp) * 2 + mf) * 32 + lane) * 8 + oct * 4 + r * 2 + e;
        d_Cfrag[ci] = c0[idx];
    }
    if (idx < 131072) d_logits[idx] = 0.0f;
}

// ------------------------- input GEMM: Xg = emb[x] @ W_ih^T + (b_ih + b_hh) -------------------------
__global__ void __launch_bounds__(256, 2) input_gemm(const int* __restrict__ x,
                                                     const float* __restrict__ b_ih,
                                                     const float* __restrict__ b_hh)
{
    extern __shared__ char smem[];
    uint32_t sb = smem_u32(smem);
    int tid = threadIdx.x;
    int bn = blockIdx.x, bm = blockIdx.y;
    int warp = tid >> 5, lane = tid & 31;
    int wm = warp & 3, wn = warp >> 2;
    int g = lane >> 2, tg = lane & 3;
    int hc0 = bn * 32;

    int* toks = (int*)smem;
    if (tid < 128) {
        int row = bm * 128 + tid;          // row = t*B + b
        toks[tid] = x[(row & 1023) * 64 + (row >> 10)];
    }
    __syncthreads();

    int r = tid >> 2, c = tid & 3;
    uint32_t offA0 = (uint32_t)(r * 80 + c * 16);
    uint32_t offA1 = (uint32_t)((r + 64) * 80 + c * 16);
    size_t aoff0 = (size_t)toks[r]      * 1024 + c * 8;
    size_t aoff1 = (size_t)toks[r + 64] * 1024 + c * 8;
    size_t boff0 = (size_t)n_of(r,      hc0) * 1024 + c * 8;
    size_t boff1 = (size_t)n_of(r + 64, hc0) * 1024 + c * 8;

    // per-lane ldmatrix offsets
    uint32_t laneA = (uint32_t)((wm * 32 + (lane & 15)) * 80 + (lane >> 4) * 16);
    uint32_t laneB = (uint32_t)((wn * 64 + ((lane >> 4) << 3) + (lane & 7)) * 80
                                + ((lane >> 3) & 1) * 16);

    float acc[2][8][4];
#pragma unroll
    for (int i = 0; i < 2; i++)
#pragma unroll
        for (int j = 0; j < 8; j++)
#pragma unroll
            for (int q = 0; q < 4; q++) acc[i][j][q] = 0.0f;

    {
        uint32_t st = sb + CTRL;
        CP16(st +         offA0, d_emb_hi + aoff0);
        CP16(st + 10240 + offA0, d_emb_lo + aoff0);
        CP16(st +         offA1, d_emb_hi + aoff1);
        CP16(st + 10240 + offA1, d_emb_lo + aoff1);
        CP16(st + 20480 + offA0, d_Wih_hi + boff0);
        CP16(st + 30720 + offA0, d_Wih_lo + boff0);
        CP16(st + 20480 + offA1, d_Wih_hi + boff1);
        CP16(st + 30720 + offA1, d_Wih_lo + boff1);
    }
    CP_COMMIT();

    for (int kt = 0; kt < 32; kt++) {
        if (kt + 1 < 32) {
            int k0 = (kt + 1) * 32;
            uint32_t st = sb + CTRL + ((kt + 1) & 1) * STAGE;
            CP16(st +         offA0, d_emb_hi + aoff0 + k0);
            CP16(st + 10240 + offA0, d_emb_lo + aoff0 + k0);
            CP16(st +         offA1, d_emb_hi + aoff1 + k0);
            CP16(st + 10240 + offA1, d_emb_lo + aoff1 + k0);
            CP16(st + 20480 + offA0, d_Wih_hi + boff0 + k0);
            CP16(st + 30720 + offA0, d_Wih_lo + boff0 + k0);
            CP16(st + 20480 + offA1, d_Wih_hi + boff1 + k0);
            CP16(st + 30720 + offA1, d_Wih_lo + boff1 + k0);
        }
        CP_COMMIT();
        CP_WAIT1();
        __syncthreads();
        uint32_t s0 = sb + CTRL + (kt & 1) * STAGE;
        gemm_chunk(acc, s0 + laneA, s0 + 10240 + laneA,
                        s0 + 20480 + laneB, s0 + 30720 + laneB);
        __syncthreads();
    }

    // epilogue: add biases, store in fragment order
#pragma unroll
    for (int mf = 0; mf < 2; mf++)
#pragma unroll
        for (int nf = 0; nf < 8; nf++) {
            int gate = nf >> 1, oct = nf & 1;
            int hcE0 = hc0 + wn * 16 + oct * 8 + 2 * tg;
            int n0 = gate * 1024 + hcE0;
            float be0 = b_ih[n0] + b_hh[n0];
            float be1 = b_ih[n0 + 1] + b_hh[n0 + 1];
            size_t off = ((((size_t)bm * 32 + bn) * 8 + warp) * 16 + mf * 8 + nf) * 128 + lane * 4;
            float4 v = make_float4(acc[mf][nf][0] + be0, acc[mf][nf][1] + be1,
                                   acc[mf][nf][2] + be0, acc[mf][nf][3] + be1);
            *(float4*)&d_Xg[off] = v;
        }
}

// ------------------------- one recurrent step -------------------------
__global__ void __launch_bounds__(256, 2) step_kernel(int t,
                                                      const float* __restrict__ Wout,
                                                      const float* __restrict__ b_out,
                                                      float* __restrict__ out)
{
    extern __shared__ char smem[];
    uint32_t sb = smem_u32(smem);
    int tid = threadIdx.x;
    int bn = blockIdx.x, bm = blockIdx.y;
    int warp = tid >> 5, lane = tid & 31;
    int wm = warp & 3, wn = warp >> 2;
    int g = lane >> 2, tg = lane & 3;
    int m0 = bm * 128, hc0 = bn * 32;

    if (t > 0 && bn == 0 && bm == 0) {
        int tb = (t - 1) << 11;
        for (int i = tid; i < 1024; i += 256) {
            float l0 = d_logits[tb + i * 2 + 0] + b_out[0];
            float l1 = d_logits[tb + i * 2 + 1] + b_out[1];
            float mx = fmaxf(l0, l1);
            float lse = mx + logf(expf(l0 - mx) + expf(l1 - mx));
            out[tb + i * 2 + 0] = l0 - lse;
            out[tb + i * 2 + 1] = l1 - lse;
        }
    }

    const __nv_bfloat16* hHi = d_h_hi[t & 1];
    const __nv_bfloat16* hLo = d_h_lo[t & 1];
    __nv_bfloat16* nHi = d_h_hi[(t + 1) & 1];
    __nv_bfloat16* nLo = d_h_lo[(t + 1) & 1];

    int r = tid >> 2, c = tid & 3;
    uint32_t offA0 = (uint32_t)(r * 80 + c * 16);
    uint32_t offA1 = (uint32_t)((r + 64) * 80 + c * 16);
    size_t aoff0 = (size_t)(m0 + r)      * 1024 + c * 8;
    size_t aoff1 = (size_t)(m0 + r + 64) * 1024 + c * 8;
    size_t boff0 = (size_t)n_of(r,      hc0) * 1024 + c * 8;
    size_t boff1 = (size_t)n_of(r + 64, hc0) * 1024 + c * 8;

    uint32_t laneA = (uint32_t)((wm * 32 + (lane & 15)) * 80 + (lane >> 4) * 16);
    uint32_t laneB = (uint32_t)((wn * 64 + ((lane >> 4) << 3) + (lane & 7)) * 80
                                + ((lane >> 3) & 1) * 16);

    float acc[2][8][4];
#pragma unroll
    for (int i = 0; i < 2; i++)
#pragma unroll
        for (int j = 0; j < 8; j++)
#pragma unroll
            for (int q = 0; q < 4; q++) acc[i][j][q] = 0.0f;

    {
        uint32_t st = sb + CTRL;
        CP16(st +         offA0, hHi + aoff0);
        CP16(st + 10240 + offA0, hLo + aoff0);
        CP16(st +         offA1, hHi + aoff1);
        CP16(st + 10240 + offA1, hLo + aoff1);
        CP16(st + 20480 + offA0, d_Whh_hi + boff0);
        CP16(st + 30720 + offA0, d_Whh_lo + boff0);
        CP16(st + 20480 + offA1, d_Whh_hi + boff1);
        CP16(st + 30720 + offA1, d_Whh_lo + boff1);
    }
    CP_COMMIT();

    for (int kt = 0; kt < 32; kt++) {
        if (kt + 1 < 32) {
            int k0 = (kt + 1) * 32;
            uint32_t st = sb + CTRL + ((kt + 1) & 1) * STAGE;
            CP16(st +         offA0, hHi + aoff0 + k0);
            CP16(st + 10240 + offA0, hLo + aoff0 + k0);
            CP16(st +         offA1, hHi + aoff1 + k0);
            CP16(st + 10240 + offA1, hLo + aoff1 + k0);
            CP16(st + 20480 + offA0, d_Whh_hi + boff0 + k0);
            CP16(st + 30720 + offA0, d_Whh_lo + boff0 + k0);
            CP16(st + 20480 + offA1, d_Whh_hi + boff1 + k0);
            CP16(st + 30720 + offA1, d_Whh_lo + boff1 + k0);
        }
        CP_COMMIT();
        CP_WAIT1();
        __syncthreads();
        uint32_t s0 = sb + CTRL + (kt & 1) * STAGE;
        gemm_chunk(acc, s0 + laneA, s0 + 10240 + laneA,
                        s0 + 20480 + laneB, s0 + 30720 + laneB);
        __syncthreads();
    }

    // ---------------- fused LSTM epilogue ----------------
    size_t xgbase = ((((size_t)(t * 8 + bm) * 32 + bn) * 8 + warp) * 16) * 128 + lane * 4;
    size_t cbase  = ((((size_t)bm * 32 + bn) * 8 + warp) * 2) * 256 + lane * 8;

    float lsum[2][2][2];
#pragma unroll
    for (int i = 0; i < 2; i++)
#pragma unroll
        for (int j = 0; j < 2; j++) { lsum[i][j][0] = 0.0f; lsum[i][j][1] = 0.0f; }

#pragma unroll
    for (int mf = 0; mf < 2; mf++) {
        float4 CP0 = *(const float4*)&d_Cfrag[cbase + mf * 256 + 0];
        float4 CP1 = *(const float4*)&d_Cfrag[cbase + mf * 256 + 4];
        float cprev[8] = {CP0.x, CP0.y, CP0.z, CP0.w, CP1.x, CP1.y, CP1.z, CP1.w};
        float cnew[8];
#pragma unroll
        for (int oct = 0; oct < 2; oct++) {
            float4 PI = *(const float4*)&d_Xg[xgbase + (size_t)(mf * 8 + 0 + oct) * 128];
            float4 PF = *(const float4*)&d_Xg[xgbase + (size_t)(mf * 8 + 2 + oct) * 128];
            float4 PG = *(const float4*)&d_Xg[xgbase + (size_t)(mf * 8 + 4 + oct) * 128];
            float4 PO = *(const float4*)&d_Xg[xgbase + (size_t)(mf * 8 + 6 + oct) * 128];
            float pri[4] = {PI.x, PI.y, PI.z, PI.w};
            float prf[4] = {PF.x, PF.y, PF.z, PF.w};
            float prg[4] = {PG.x, PG.y, PG.z, PG.w};
            float pro[4] = {PO.x, PO.y, PO.z, PO.w};
#pragma unroll
            for (int q = 0; q < 4; q++) {
                int rr = q >> 1, e = q & 1;
                float I = acc[mf][0 + oct][q] + pri[q];
                float F = acc[mf][2 + oct][q] + prf[q];
                float G = acc[mf][4 + oct][q] + prg[q];
                float O = acc[mf][6 + oct][q] + pro[q];
                float si = 1.0f / (1.0f + expf(-I));
                float sf = 1.0f / (1.0f + expf(-F));
                float so = 1.0f / (1.0f + expf(-O));
                float c2 = sf * cprev[oct * 4 + q] + si * tanhf(G);
                float h2 = so * tanhf(c2);
                cnew[oct * 4 + q] = c2;
                int b  = m0 + wm * 32 + mf * 16 + rr * 8 + g;
                int hc = hc0 + wn * 16 + oct * 8 + 2 * tg + e;
                __nv_bfloat16 hi = __float2bfloat16(h2);
                nHi[b * 1024 + hc] = hi;
                nLo[b * 1024 + hc] = __float2bfloat16(h2 - __bfloat162float(hi));
                lsum[mf][rr][0] += c2 * Wout[hc];
                lsum[mf][rr][1] += c2 * Wout[1024 + hc];
            }
        }
        *(float4*)&d_Cfrag[cbase + mf * 256 + 0] = make_float4(cnew[0], cnew[1], cnew[2], cnew[3]);
        *(float4*)&d_Cfrag[cbase + mf * 256 + 4] = make_float4(cnew[4], cnew[5], cnew[6], cnew[7]);
    }

#pragma unroll
    for (int mf = 0; mf < 2; mf++)
#pragma unroll
        for (int rr = 0; rr < 2; rr++)
#pragma unroll
            for (int cls = 0; cls < 2; cls++) {
                float v = lsum[mf][rr][cls];
                v += __shfl_xor_sync(0xffffffffu, v, 1);
                v += __shfl_xor_sync(0xffffffffu, v, 2);
                if (tg == 0) {
                    int b = m0 + wm * 32 + mf * 16 + rr * 8 + g;
                    atomicAdd(&d_logits[(t << 11) + b * 2 + cls], v);
                }
            }
}

// ------------------------- finalize t=63 + out_final -------------------------
__global__ void final_kernel(const float* __restrict__ b_out, float* __restrict__ out)
{
    int i = blockIdx.x * 256 + threadIdx.x;
    if (i < 1024) {
        int tb = 63 << 11;
        float l0 = d_logits[tb + i * 2 + 0] + b_out[0];
        float l1 = d_logits[tb + i * 2 + 1] + b_out[1];
        float mx = fmaxf(l0, l1);
        float lse = mx + logf(expf(l0 - mx) + expf(l1 - mx));
        out[tb + i * 2 + 0] = l0 - lse;
        out[tb + i * 2 + 1] = l1 - lse;
        out[131072 + i * 2 + 0] = l0;
        out[131072 + i * 2 + 1] = l1;
    }
}

// ------------------------- launch -------------------------
extern "C" void kernel_launch(void* const* d_in, const int* in_sizes, int n_in,
                              void* d_out, int out_size)
{
    (void)in_sizes; (void)n_in; (void)out_size;
    const int*   x    = (const int*)d_in[0];
    const float* emb  = (const float*)d_in[1];
    const float* Wih  = (const float*)d_in[2];
    const float* Whh  = (const float*)d_in[3];
    const float* bih  = (const float*)d_in[4];
    const float* bhh  = (const float*)d_in[5];
    const float* Wout = (const float*)d_in[6];
    const float* bout = (const float*)d_in[7];
    const float* h0   = (const float*)d_in[8];
    const float* c0   = (const float*)d_in[9];
    float* out = (float*)d_out;

    cudaFuncSetAttribute(input_gemm, cudaFuncAttributeMaxDynamicSharedMemorySize, SMEM_BYTES);
    cudaFuncSetAttribute(step_kernel, cudaFuncAttributeMaxDynamicSharedMemorySize, SMEM_BYTES);

    init_kernel<<<16384, 256>>>(Wih, Whh, emb, h0, c0);
    input_gemm<<<dim3(32, 512), 256, SMEM_BYTES>>>(x, bih, bhh);
    for (int t = 0; t < 64; t++)
        step_kernel<<<dim3(32, 8), 256, SMEM_BYTES>>>(t, Wout, bout, out);
    final_kernel<<<4, 256>>>(bout, out);
}

// round 5
// speedup vs baseline: 3.1415x; 1.5506x over previous
#include <cuda_runtime.h>
#include <cuda_bf16.h>
#include <cstdint>

// B=1024, T=64, E=H=1024, 4H=4096, NCLS=2, VOCAB=50000
// INT8 IMMA (m16n8k32.s8) fixed-point-split GEMM engine.
//   x ~= s*(q1*256 + q0),  gates = sA*sB*(65536*T11 + 256*(T10+T01))
// cp.async double-buffered, ldmatrix fragment loads, CTA tile 128x128 (K-chunk 64),
// gate-interleaved N -> fused LSTM cell + classifier epilogue.

#define CTRL  1024
#define STAGE 40960                    // A1 10240 | A0 10240 | B1 10240 | B0 10240
#define SMEM_BYTES (CTRL + 2 * STAGE)  // 82944
#define QMAXF 32512.0f

// ------------------------- static device scratch -------------------------
__device__ float d_Xg[268435456];      // pre-gates (+bias), MMA fragment order
__device__ float d_Cfrag[1048576];     // cell state, fragment order
__device__ __align__(256) char d_hq1[2][1048576];
__device__ __align__(256) char d_hq0[2][1048576];
__device__ __align__(256) char d_Wihq1[4194304];
__device__ __align__(256) char d_Wihq0[4194304];
__device__ __align__(256) char d_Whhq1[4194304];
__device__ __align__(256) char d_Whhq0[4194304];
__device__ __align__(256) char d_embq1[51200000];
__device__ __align__(256) char d_embq0[51200000];
__device__ unsigned d_absmax[4];       // 0=Wih 1=Whh 2=emb 3=h0
__device__ float d_logits[131072];     // [T][B][2]

// ------------------------- helpers -------------------------
__device__ __forceinline__ uint32_t smem_u32(const void* p) {
    uint32_t a;
    asm("{ .reg .u64 t; cvta.to.shared.u64 t, %1; cvt.u32.u64 %0, t; }" : "=r"(a) : "l"(p));
    return a;
}

#define CP16(dst, src) \
    asm volatile("cp.async.cg.shared.global [%0], [%1], 16;" :: "r"(dst), "l"(src) : "memory")
#define CP_COMMIT() asm volatile("cp.async.commit_group;" ::: "memory")
#define CP_WAIT1()  asm volatile("cp.async.wait_group 1;" ::: "memory")

#define LDSM4(r0, r1, r2, r3, addr) \
    asm volatile("ldmatrix.sync.aligned.m8n8.x4.shared.b16 {%0,%1,%2,%3}, [%4];" \
        : "=r"(r0), "=r"(r1), "=r"(r2), "=r"(r3) : "r"(addr))

__device__ __forceinline__ void mma_s8(int* d, const uint32_t* a, const uint32_t* b) {
    asm volatile(
        "mma.sync.aligned.m16n8k32.row.col.s32.s8.s8.s32 "
        "{%0,%1,%2,%3}, {%4,%5,%6,%7}, {%8,%9}, {%0,%1,%2,%3};\n"
        : "+r"(d[0]), "+r"(d[1]), "+r"(d[2]), "+r"(d[3])
        : "r"(a[0]), "r"(a[1]), "r"(a[2]), "r"(a[3]), "r"(b[0]), "r"(b[1]));
}

// gate-interleaved column mapping: CTA-local col cl in [0,128) -> global n in [0,4096)
__device__ __forceinline__ int n_of(int cl, int hc0) {
    int wn_  = cl >> 6;
    int rem  = cl & 63;
    int nf   = rem >> 3;
    int f    = rem & 7;
    int gate = nf >> 1;
    int oct  = nf & 1;
    return gate * 1024 + hc0 + wn_ * 16 + oct * 8 + f;
}

__device__ __forceinline__ void quant16(float v, float inv_s, char* a1, char* a0) {
    int q = __float2int_rn(v * inv_s);
    q = max(-32512, min(32512, q));
    int q1 = (q + 128) >> 8;
    *a1 = (char)q1;
    *a0 = (char)(q - (q1 << 8));
}

// one K=64 chunk (2x k32 IMMA sub-steps), 3-term fixed-point split.
// Rows are 64 bytes of s8 at pitch 80 (same smem geometry as the bf16 version:
// a 32-byte k32 run occupies the same bytes as 16 bf16, so LDSM addressing is identical).
__device__ __forceinline__ void gemm_chunk_i8(
    int acc1[2][8][4], int acc2[2][8][4],
    uint32_t aH, uint32_t aL, uint32_t bH, uint32_t bL)
{
#pragma unroll
    for (int ks = 0; ks < 2; ks++) {
        uint32_t off = ks * 32;
        uint32_t a1[2][4], a0[2][4];
        LDSM4(a1[0][0], a1[0][1], a1[0][2], a1[0][3], aH + off);
        LDSM4(a1[1][0], a1[1][1], a1[1][2], a1[1][3], aH + 1280 + off);
        LDSM4(a0[0][0], a0[0][1], a0[0][2], a0[0][3], aL + off);
        LDSM4(a0[1][0], a0[1][1], a0[1][2], a0[1][3], aL + 1280 + off);
#pragma unroll
        for (int nfp = 0; nfp < 4; nfp++) {
            uint32_t b1[4], b0[4];
            LDSM4(b1[0], b1[1], b1[2], b1[3], bH + nfp * 1280 + off);
            LDSM4(b0[0], b0[1], b0[2], b0[3], bL + nfp * 1280 + off);
#pragma unroll
            for (int mf = 0; mf < 2; mf++) {
                mma_s8(acc1[mf][2 * nfp    ], a1[mf], b1    );   // T11
                mma_s8(acc2[mf][2 * nfp    ], a1[mf], b0    );   // T10
                mma_s8(acc2[mf][2 * nfp    ], a0[mf], b1    );   // T01
                mma_s8(acc1[mf][2 * nfp + 1], a1[mf], b1 + 2);
                mma_s8(acc2[mf][2 * nfp + 1], a1[mf], b0 + 2);
                mma_s8(acc2[mf][2 * nfp + 1], a0[mf], b1 + 2);
            }
        }
    }
}

// ------------------------- absmax pre-pass -------------------------
__global__ void zero_absmax() {
    if (threadIdx.x < 4) d_absmax[threadIdx.x] = 0u;
}

__global__ void absmax_kernel(const float* __restrict__ Wih, const float* __restrict__ Whh,
                              const float* __restrict__ emb, const float* __restrict__ h0)
{
    long g = blockIdx.x * 256 + threadIdx.x;
    const long stride = 262144;
    float m0 = 0.f, m1 = 0.f, m2 = 0.f, m3 = 0.f;
    for (long i = g; i < 4194304L; i += stride) {
        m0 = fmaxf(m0, fabsf(Wih[i]));
        m1 = fmaxf(m1, fabsf(Whh[i]));
    }
    for (long i = g; i < 51200000L; i += stride) m2 = fmaxf(m2, fabsf(emb[i]));
    for (long i = g; i < 1048576L; i += stride)  m3 = fmaxf(m3, fabsf(h0[i]));
#pragma unroll
    for (int off = 16; off > 0; off >>= 1) {
        m0 = fmaxf(m0, __shfl_xor_sync(0xffffffffu, m0, off));
        m1 = fmaxf(m1, __shfl_xor_sync(0xffffffffu, m1, off));
        m2 = fmaxf(m2, __shfl_xor_sync(0xffffffffu, m2, off));
        m3 = fmaxf(m3, __shfl_xor_sync(0xffffffffu, m3, off));
    }
    if ((threadIdx.x & 31) == 0) {
        atomicMax(&d_absmax[0], __float_as_uint(m0));
        atomicMax(&d_absmax[1], __float_as_uint(m1));
        atomicMax(&d_absmax[2], __float_as_uint(m2));
        atomicMax(&d_absmax[3], __float_as_uint(m3));
    }
}

// ------------------------- init: quantize weights/emb/h0, layout c0 -------------------------
__global__ void init_quant(const float* __restrict__ Wih, const float* __restrict__ Whh,
                           const float* __restrict__ emb,
                           const float* __restrict__ h0,  const float* __restrict__ c0)
{
    int idx = blockIdx.x * 256 + threadIdx.x;
    float iWih = QMAXF / fmaxf(__uint_as_float(d_absmax[0]), 1e-20f);
    float iWhh = QMAXF / fmaxf(__uint_as_float(d_absmax[1]), 1e-20f);
    float iEmb = QMAXF / fmaxf(__uint_as_float(d_absmax[2]), 1e-20f);
    float iH0  = QMAXF / fmaxf(__uint_as_float(d_absmax[3]), 1e-20f);

    if (idx < 4194304) {
        quant16(Wih[idx], iWih, &d_Wihq1[idx], &d_Wihq0[idx]);
        quant16(Whh[idx], iWhh, &d_Whhq1[idx], &d_Whhq0[idx]);
    }
    for (long i = idx; i < 51200000L; i += 4194304L)
        quant16(emb[i], iEmb, &d_embq1[i], &d_embq0[i]);
    if (idx < 1048576) {
        quant16(h0[idx], iH0, &d_hq1[0][idx], &d_hq0[0][idx]);
        int b = idx >> 10, hc = idx & 1023;
        int bm = b >> 7, wm = (b >> 5) & 3, mf = (b >> 4) & 1, r = (b >> 3) & 1, g = b & 7;
        int bn = hc >> 5, wn = (hc >> 4) & 1, oct = (hc >> 3) & 1, tg = (hc >> 1) & 3, e = hc & 1;
        int warp = wn * 4 + wm, lane = g * 4 + tg;
        int ci = ((((bm * 32 + bn) * 8 + warp) * 2 + mf) * 32 + lane) * 8 + oct * 4 + r * 2 + e;
        d_Cfrag[ci] = c0[idx];
    }
    if (idx < 131072) d_logits[idx] = 0.0f;
}

// ------------------------- input GEMM: Xg = emb[x] @ W_ih^T + (b_ih + b_hh) -------------------------
__global__ void __launch_bounds__(256) input_gemm(const int* __restrict__ x,
                                                  const float* __restrict__ b_ih,
                                                  const float* __restrict__ b_hh)
{
    extern __shared__ char smem[];
    uint32_t sb = smem_u32(smem);
    int tid = threadIdx.x;
    int bn = blockIdx.x, bm = blockIdx.y;
    int warp = tid >> 5, lane = tid & 31;
    int wm = warp & 3, wn = warp >> 2;
    int g = lane >> 2, tg = lane & 3;
    int hc0 = bn * 32;

    float sAB = (__uint_as_float(d_absmax[2]) / QMAXF) * (__uint_as_float(d_absmax[0]) / QMAXF);
    float sHIc = sAB * 65536.0f, sLOc = sAB * 256.0f;

    int* toks = (int*)smem;
    if (tid < 128) {
        int row = bm * 128 + tid;          // row = t*B + b
        toks[tid] = x[(row & 1023) * 64 + (row >> 10)];
    }
    __syncthreads();

    int r = tid >> 2, c = tid & 3;
    uint32_t offA0 = (uint32_t)(r * 80 + c * 16);
    uint32_t offA1 = (uint32_t)((r + 64) * 80 + c * 16);
    size_t aoff0 = (size_t)toks[r]      * 1024 + c * 16;
    size_t aoff1 = (size_t)toks[r + 64] * 1024 + c * 16;
    size_t boff0 = (size_t)n_of(r,      hc0) * 1024 + c * 16;
    size_t boff1 = (size_t)n_of(r + 64, hc0) * 1024 + c * 16;

    uint32_t laneA = (uint32_t)((wm * 32 + (lane & 15)) * 80 + (lane >> 4) * 16);
    uint32_t laneB = (uint32_t)((wn * 64 + ((lane >> 4) << 3) + (lane & 7)) * 80
                                + ((lane >> 3) & 1) * 16);

    int acc1[2][8][4], acc2[2][8][4];
#pragma unroll
    for (int i = 0; i < 2; i++)
#pragma unroll
        for (int j = 0; j < 8; j++)
#pragma unroll
            for (int q = 0; q < 4; q++) { acc1[i][j][q] = 0; acc2[i][j][q] = 0; }

    {
        uint32_t st = sb + CTRL;
        CP16(st +         offA0, d_embq1 + aoff0);
        CP16(st + 10240 + offA0, d_embq0 + aoff0);
        CP16(st +         offA1, d_embq1 + aoff1);
        CP16(st + 10240 + offA1, d_embq0 + aoff1);
        CP16(st + 20480 + offA0, d_Wihq1 + boff0);
        CP16(st + 30720 + offA0, d_Wihq0 + boff0);
        CP16(st + 20480 + offA1, d_Wihq1 + boff1);
        CP16(st + 30720 + offA1, d_Wihq0 + boff1);
    }
    CP_COMMIT();

    for (int kt = 0; kt < 16; kt++) {
        if (kt + 1 < 16) {
            int k0 = (kt + 1) * 64;
            uint32_t st = sb + CTRL + ((kt + 1) & 1) * STAGE;
            CP16(st +         offA0, d_embq1 + aoff0 + k0);
            CP16(st + 10240 + offA0, d_embq0 + aoff0 + k0);
            CP16(st +         offA1, d_embq1 + aoff1 + k0);
            CP16(st + 10240 + offA1, d_embq0 + aoff1 + k0);
            CP16(st + 20480 + offA0, d_Wihq1 + boff0 + k0);
            CP16(st + 30720 + offA0, d_Wihq0 + boff0 + k0);
            CP16(st + 20480 + offA1, d_Wihq1 + boff1 + k0);
            CP16(st + 30720 + offA1, d_Wihq0 + boff1 + k0);
        }
        CP_COMMIT();
        CP_WAIT1();
        __syncthreads();
        uint32_t s0 = sb + CTRL + (kt & 1) * STAGE;
        gemm_chunk_i8(acc1, acc2, s0 + laneA, s0 + 10240 + laneA,
                                  s0 + 20480 + laneB, s0 + 30720 + laneB);
        __syncthreads();
    }

    // epilogue: combine terms, add biases, store in fragment order
#pragma unroll
    for (int mf = 0; mf < 2; mf++)
#pragma unroll
        for (int nf = 0; nf < 8; nf++) {
            int gate = nf >> 1, oct = nf & 1;
            int hcE0 = hc0 + wn * 16 + oct * 8 + 2 * tg;
            int n0 = gate * 1024 + hcE0;
            float be0 = b_ih[n0] + b_hh[n0];
            float be1 = b_ih[n0 + 1] + b_hh[n0 + 1];
            size_t off = ((((size_t)bm * 32 + bn) * 8 + warp) * 16 + mf * 8 + nf) * 128 + lane * 4;
            float4 v;
            v.x = sHIc * (float)acc1[mf][nf][0] + sLOc * (float)acc2[mf][nf][0] + be0;
            v.y = sHIc * (float)acc1[mf][nf][1] + sLOc * (float)acc2[mf][nf][1] + be1;
            v.z = sHIc * (float)acc1[mf][nf][2] + sLOc * (float)acc2[mf][nf][2] + be0;
            v.w = sHIc * (float)acc1[mf][nf][3] + sLOc * (float)acc2[mf][nf][3] + be1;
            *(float4*)&d_Xg[off] = v;
        }
}

// ------------------------- one recurrent step -------------------------
__global__ void __launch_bounds__(256) step_kernel(int t,
                                                   const float* __restrict__ Wout,
                                                   const float* __restrict__ b_out,
                                                   float* __restrict__ out)
{
    extern __shared__ char smem[];
    uint32_t sb = smem_u32(smem);
    int tid = threadIdx.x;
    int bn = blockIdx.x, bm = blockIdx.y;
    int warp = tid >> 5, lane = tid & 31;
    int wm = warp & 3, wn = warp >> 2;
    int g = lane >> 2, tg = lane & 3;
    int m0 = bm * 128, hc0 = bn * 32;

    if (t > 0 && bn == 0 && bm == 0) {
        int tb = (t - 1) << 11;
        for (int i = tid; i < 1024; i += 256) {
            float l0 = d_logits[tb + i * 2 + 0] + b_out[0];
            float l1 = d_logits[tb + i * 2 + 1] + b_out[1];
            float mx = fmaxf(l0, l1);
            float lse = mx + logf(expf(l0 - mx) + expf(l1 - mx));
            out[tb + i * 2 + 0] = l0 - lse;
            out[tb + i * 2 + 1] = l1 - lse;
        }
    }

    float sh  = (t == 0) ? (__uint_as_float(d_absmax[3]) / QMAXF) : (1.0f / QMAXF);
    float sAB = sh * (__uint_as_float(d_absmax[1]) / QMAXF);
    float sHIc = sAB * 65536.0f, sLOc = sAB * 256.0f;

    const char* hQ1 = d_hq1[t & 1];
    const char* hQ0 = d_hq0[t & 1];
    char* nQ1 = d_hq1[(t + 1) & 1];
    char* nQ0 = d_hq0[(t + 1) & 1];

    int r = tid >> 2, c = tid & 3;
    uint32_t offA0 = (uint32_t)(r * 80 + c * 16);
    uint32_t offA1 = (uint32_t)((r + 64) * 80 + c * 16);
    size_t aoff0 = (size_t)(m0 + r)      * 1024 + c * 16;
    size_t aoff1 = (size_t)(m0 + r + 64) * 1024 + c * 16;
    size_t boff0 = (size_t)n_of(r,      hc0) * 1024 + c * 16;
    size_t boff1 = (size_t)n_of(r + 64, hc0) * 1024 + c * 16;

    uint32_t laneA = (uint32_t)((wm * 32 + (lane & 15)) * 80 + (lane >> 4) * 16);
    uint32_t laneB = (uint32_t)((wn * 64 + ((lane >> 4) << 3) + (lane & 7)) * 80
                                + ((lane >> 3) & 1) * 16);

    int acc1[2][8][4], acc2[2][8][4];
#pragma unroll
    for (int i = 0; i < 2; i++)
#pragma unroll
        for (int j = 0; j < 8; j++)
#pragma unroll
            for (int q = 0; q < 4; q++) { acc1[i][j][q] = 0; acc2[i][j][q] = 0; }

    {
        uint32_t st = sb + CTRL;
        CP16(st +         offA0, hQ1 + aoff0);
        CP16(st + 10240 + offA0, hQ0 + aoff0);
        CP16(st +         offA1, hQ1 + aoff1);
        CP16(st + 10240 + offA1, hQ0 + aoff1);
        CP16(st + 20480 + offA0, d_Whhq1 + boff0);
        CP16(st + 30720 + offA0, d_Whhq0 + boff0);
        CP16(st + 20480 + offA1, d_Whhq1 + boff1);
        CP16(st + 30720 + offA1, d_Whhq0 + boff1);
    }
    CP_COMMIT();

    for (int kt = 0; kt < 16; kt++) {
        if (kt + 1 < 16) {
            int k0 = (kt + 1) * 64;
            uint32_t st = sb + CTRL + ((kt + 1) & 1) * STAGE;
            CP16(st +         offA0, hQ1 + aoff0 + k0);
            CP16(st + 10240 + offA0, hQ0 + aoff0 + k0);
            CP16(st +         offA1, hQ1 + aoff1 + k0);
            CP16(st + 10240 + offA1, hQ0 + aoff1 + k0);
            CP16(st + 20480 + offA0, d_Whhq1 + boff0 + k0);
            CP16(st + 30720 + offA0, d_Whhq0 + boff0 + k0);
            CP16(st + 20480 + offA1, d_Whhq1 + boff1 + k0);
            CP16(st + 30720 + offA1, d_Whhq0 + boff1 + k0);
        }
        CP_COMMIT();
        CP_WAIT1();
        __syncthreads();
        uint32_t s0 = sb + CTRL + (kt & 1) * STAGE;
        gemm_chunk_i8(acc1, acc2, s0 + laneA, s0 + 10240 + laneA,
                                  s0 + 20480 + laneB, s0 + 30720 + laneB);
        __syncthreads();
    }

    // ---------------- fused LSTM epilogue ----------------
    size_t xgbase = ((((size_t)(t * 8 + bm) * 32 + bn) * 8 + warp) * 16) * 128 + lane * 4;
    size_t cbase  = ((((size_t)bm * 32 + bn) * 8 + warp) * 2) * 256 + lane * 8;

    float lsum[2][2][2];
#pragma unroll
    for (int i = 0; i < 2; i++)
#pragma unroll
        for (int j = 0; j < 2; j++) { lsum[i][j][0] = 0.0f; lsum[i][j][1] = 0.0f; }

#pragma unroll
    for (int mf = 0; mf < 2; mf++) {
        float4 CP0 = *(const float4*)&d_Cfrag[cbase + mf * 256 + 0];
        float4 CP1 = *(const float4*)&d_Cfrag[cbase + mf * 256 + 4];
        float cprev[8] = {CP0.x, CP0.y, CP0.z, CP0.w, CP1.x, CP1.y, CP1.z, CP1.w};
        float cnew[8];
#pragma unroll
        for (int oct = 0; oct < 2; oct++) {
            float4 PI = *(const float4*)&d_Xg[xgbase + (size_t)(mf * 8 + 0 + oct) * 128];
            float4 PF = *(const float4*)&d_Xg[xgbase + (size_t)(mf * 8 + 2 + oct) * 128];
            float4 PG = *(const float4*)&d_Xg[xgbase + (size_t)(mf * 8 + 4 + oct) * 128];
            float4 PO = *(const float4*)&d_Xg[xgbase + (size_t)(mf * 8 + 6 + oct) * 128];
            float pri[4] = {PI.x, PI.y, PI.z, PI.w};
            float prf[4] = {PF.x, PF.y, PF.z, PF.w};
            float prg[4] = {PG.x, PG.y, PG.z, PG.w};
            float pro[4] = {PO.x, PO.y, PO.z, PO.w};
#pragma unroll
            for (int q = 0; q < 4; q++) {
                int rr = q >> 1, e = q & 1;
                float I = sHIc * (float)acc1[mf][0 + oct][q] + sLOc * (float)acc2[mf][0 + oct][q] + pri[q];
                float F = sHIc * (float)acc1[mf][2 + oct][q] + sLOc * (float)acc2[mf][2 + oct][q] + prf[q];
                float G = sHIc * (float)acc1[mf][4 + oct][q] + sLOc * (float)acc2[mf][4 + oct][q] + prg[q];
                float O = sHIc * (float)acc1[mf][6 + oct][q] + sLOc * (float)acc2[mf][6 + oct][q] + pro[q];
                float si = 1.0f / (1.0f + expf(-I));
                float sf = 1.0f / (1.0f + expf(-F));
                float so = 1.0f / (1.0f + expf(-O));
                float c2 = sf * cprev[oct * 4 + q] + si * tanhf(G);
                float h2 = so * tanhf(c2);
                cnew[oct * 4 + q] = c2;
                int b  = m0 + wm * 32 + mf * 16 + rr * 8 + g;
                int hc = hc0 + wn * 16 + oct * 8 + 2 * tg + e;
                int qh = __float2int_rn(h2 * QMAXF);
                int qh1 = (qh + 128) >> 8;
                nQ1[b * 1024 + hc] = (char)qh1;
                nQ0[b * 1024 + hc] = (char)(qh - (qh1 << 8));
                lsum[mf][rr][0] += c2 * Wout[hc];
                lsum[mf][rr][1] += c2 * Wout[1024 + hc];
            }
        }
        *(float4*)&d_Cfrag[cbase + mf * 256 + 0] = make_float4(cnew[0], cnew[1], cnew[2], cnew[3]);
        *(float4*)&d_Cfrag[cbase + mf * 256 + 4] = make_float4(cnew[4], cnew[5], cnew[6], cnew[7]);
    }

#pragma unroll
    for (int mf = 0; mf < 2; mf++)
#pragma unroll
        for (int rr = 0; rr < 2; rr++)
#pragma unroll
            for (int cls = 0; cls < 2; cls++) {
                float v = lsum[mf][rr][cls];
                v += __shfl_xor_sync(0xffffffffu, v, 1);
                v += __shfl_xor_sync(0xffffffffu, v, 2);
                if (tg == 0) {
                    int b = m0 + wm * 32 + mf * 16 + rr * 8 + g;
                    atomicAdd(&d_logits[(t << 11) + b * 2 + cls], v);
                }
            }
}

// ------------------------- finalize t=63 + out_final -------------------------
__global__ void final_kernel(const float* __restrict__ b_out, float* __restrict__ out)
{
    int i = blockIdx.x * 256 + threadIdx.x;
    if (i < 1024) {
        int tb = 63 << 11;
        float l0 = d_logits[tb + i * 2 + 0] + b_out[0];
        float l1 = d_logits[tb + i * 2 + 1] + b_out[1];
        float mx = fmaxf(l0, l1);
        float lse = mx + logf(expf(l0 - mx) + expf(l1 - mx));
        out[tb + i * 2 + 0] = l0 - lse;
        out[tb + i * 2 + 1] = l1 - lse;
        out[131072 + i * 2 + 0] = l0;
        out[131072 + i * 2 + 1] = l1;
    }
}

// ------------------------- launch -------------------------
extern "C" void kernel_launch(void* const* d_in, const int* in_sizes, int n_in,
                              void* d_out, int out_size)
{
    (void)in_sizes; (void)n_in; (void)out_size;
    const int*   x    = (const int*)d_in[0];
    const float* emb  = (const float*)d_in[1];
    const float* Wih  = (const float*)d_in[2];
    const float* Whh  = (const float*)d_in[3];
    const float* bih  = (const float*)d_in[4];
    const float* bhh  = (const float*)d_in[5];
    const float* Wout = (const float*)d_in[6];
    const float* bout = (const float*)d_in[7];
    const float* h0   = (const float*)d_in[8];
    const float* c0   = (const float*)d_in[9];
    float* out = (float*)d_out;

    cudaFuncSetAttribute(input_gemm, cudaFuncAttributeMaxDynamicSharedMemorySize, SMEM_BYTES);
    cudaFuncSetAttribute(step_kernel, cudaFuncAttributeMaxDynamicSharedMemorySize, SMEM_BYTES);

    zero_absmax<<<1, 32>>>();
    absmax_kernel<<<1024, 256>>>(Wih, Whh, emb, h0);
    init_quant<<<16384, 256>>>(Wih, Whh, emb, h0, c0);
    input_gemm<<<dim3(32, 512), 256, SMEM_BYTES>>>(x, bih, bhh);
    for (int t = 0; t < 64; t++)
        step_kernel<<<dim3(32, 8), 256, SMEM_BYTES>>>(t, Wout, bout, out);
    final_kernel<<<4, 256>>>(bout, out);
}

// round 7
// speedup vs baseline: 3.4596x; 1.1012x over previous
#include <cuda_runtime.h>
#include <cuda_bf16.h>
#include <cstdint>

// B=1024, T=64, E=H=1024, 4H=4096, NCLS=2, VOCAB=50000
// INT8 IMMA (m16n8k32.s8) fixed-point-split engine.
//   x ~= s*(q1*256 + q0),  gates = sA*sB*(65536*T11 + 256*(T10+T01))
// 512 threads / 16 warps, warp tile 32x32, CTA tile 128x128 (K-chunk 64),
// cp.async double-buffered, ldmatrix loads, dependency-spaced MMA ordering,
// gate-per-nf mapping -> fused LSTM cell + classifier epilogue.

#define CTRL  1024
#define STAGE 40960                    // A1 10240 | A0 10240 | B1 10240 | B0 10240
#define SMEM_BYTES (CTRL + 2 * STAGE)  // 82944
#define QMAXF 32512.0f

// ------------------------- static device scratch -------------------------
__device__ float d_Xg[268435456];      // pre-gates (+bias), fragment order
__device__ float d_Cfrag[1048576];     // cell state, fragment order
__device__ __align__(256) signed char d_hq1[2][1048576];
__device__ __align__(256) signed char d_hq0[2][1048576];
__device__ __align__(256) signed char d_Wihq1[4194304];
__device__ __align__(256) signed char d_Wihq0[4194304];
__device__ __align__(256) signed char d_Whhq1[4194304];
__device__ __align__(256) signed char d_Whhq0[4194304];
__device__ __align__(256) signed char d_embq1[51200000];
__device__ __align__(256) signed char d_embq0[51200000];
__device__ unsigned d_absmax[4];       // 0=Wih 1=Whh 2=emb 3=h0
__device__ float d_logits[131072];     // [T][B][2]

// ------------------------- helpers -------------------------
__device__ __forceinline__ uint32_t smem_u32(const void* p) {
    uint32_t a;
    asm("{ .reg .u64 t; cvta.to.shared.u64 t, %1; cvt.u32.u64 %0, t; }" : "=r"(a) : "l"(p));
    return a;
}

#define CP16(dst, src) \
    asm volatile("cp.async.cg.shared.global [%0], [%1], 16;" :: "r"(dst), "l"(src) : "memory")
#define CP_COMMIT() asm volatile("cp.async.commit_group;" ::: "memory")
#define CP_WAIT1()  asm volatile("cp.async.wait_group 1;" ::: "memory")

#define LDSM4(r0, r1, r2, r3, addr) \
    asm volatile("ldmatrix.sync.aligned.m8n8.x4.shared.b16 {%0,%1,%2,%3}, [%4];" \
        : "=r"(r0), "=r"(r1), "=r"(r2), "=r"(r3) : "r"(addr))

__device__ __forceinline__ void mma_s8(int* d, const uint32_t* a, const uint32_t* b) {
    asm volatile(
        "mma.sync.aligned.m16n8k32.row.col.s32.s8.s8.s32 "
        "{%0,%1,%2,%3}, {%4,%5,%6,%7}, {%8,%9}, {%0,%1,%2,%3};\n"
        : "+r"(d[0]), "+r"(d[1]), "+r"(d[2]), "+r"(d[3])
        : "r"(a[0]), "r"(a[1]), "r"(a[2]), "r"(a[3]), "r"(b[0]), "r"(b[1]));
}

// CTA-local col cl in [0,128) -> global n: cl = wn*32 + nf*8 + f, nf = gate
__device__ __forceinline__ int n_of(int cl, int hc0) {
    int wn_ = cl >> 5;
    int nf  = (cl >> 3) & 3;
    int f   = cl & 7;
    return nf * 1024 + hc0 + wn_ * 8 + f;
}

__device__ __forceinline__ void quant16(float v, float inv_s, signed char* a1, signed char* a0) {
    int q = __float2int_rn(v * inv_s);
    q = max(-32512, min(32512, q));
    int q1 = (q + 128) >> 8;
    *a1 = (signed char)q1;
    *a0 = (signed char)(q - (q1 << 8));
}
__device__ __forceinline__ void quant16x4(float4 v, float inv_s, char4* o1, char4* o0) {
    char4 c1, c0;
    quant16(v.x, inv_s, &c1.x, &c0.x);
    quant16(v.y, inv_s, &c1.y, &c0.y);
    quant16(v.z, inv_s, &c1.z, &c0.z);
    quant16(v.w, inv_s, &c1.w, &c0.w);
    *o1 = c1; *o0 = c0;
}

// one K=64 chunk (2x k32), 3-term split, warp tile 32x32, dependency-spaced order
__device__ __forceinline__ void gemm_chunk_i8(
    int acc1[2][4][4], int acc2[2][4][4],
    uint32_t aH, uint32_t aL, uint32_t bH, uint32_t bL)
{
#pragma unroll
    for (int ks = 0; ks < 2; ks++) {
        uint32_t off = ks * 32;
        uint32_t a1[2][4], a0[2][4], b1[8], b0[8];
        LDSM4(a1[0][0], a1[0][1], a1[0][2], a1[0][3], aH + off);
        LDSM4(a1[1][0], a1[1][1], a1[1][2], a1[1][3], aH + 1280 + off);
        LDSM4(a0[0][0], a0[0][1], a0[0][2], a0[0][3], aL + off);
        LDSM4(a0[1][0], a0[1][1], a0[1][2], a0[1][3], aL + 1280 + off);
        LDSM4(b1[0], b1[1], b1[2], b1[3], bH + off);
        LDSM4(b1[4], b1[5], b1[6], b1[7], bH + 1280 + off);
        LDSM4(b0[0], b0[1], b0[2], b0[3], bL + off);
        LDSM4(b0[4], b0[5], b0[6], b0[7], bL + 1280 + off);
        // 8x T11, then 8x T10, then 8x T01 -> same-acc distance = 8
#pragma unroll
        for (int mf = 0; mf < 2; mf++)
#pragma unroll
            for (int nf = 0; nf < 4; nf++)
                mma_s8(acc1[mf][nf], a1[mf], b1 + nf * 2);
#pragma unroll
        for (int mf = 0; mf < 2; mf++)
#pragma unroll
            for (int nf = 0; nf < 4; nf++)
                mma_s8(acc2[mf][nf], a1[mf], b0 + nf * 2);
#pragma unroll
        for (int mf = 0; mf < 2; mf++)
#pragma unroll
            for (int nf = 0; nf < 4; nf++)
                mma_s8(acc2[mf][nf], a0[mf], b1 + nf * 2);
    }
}

// ------------------------- absmax pre-pass -------------------------
__global__ void zero_absmax() {
    if (threadIdx.x < 4) d_absmax[threadIdx.x] = 0u;
}

__device__ __forceinline__ float amax4(float4 v) {
    return fmaxf(fmaxf(fabsf(v.x), fabsf(v.y)), fmaxf(fabsf(v.z), fabsf(v.w)));
}

__global__ void absmax_kernel(const float* __restrict__ Wih, const float* __restrict__ Whh,
                              const float* __restrict__ emb, const float* __restrict__ h0)
{
    long g = blockIdx.x * 256 + threadIdx.x;
    const long stride = 262144;
    float m0 = 0.f, m1 = 0.f, m2 = 0.f, m3 = 0.f;
    for (long i = g; i < 1048576L; i += stride) {
        m0 = fmaxf(m0, amax4(*(const float4*)&Wih[i * 4]));
        m1 = fmaxf(m1, amax4(*(const float4*)&Whh[i * 4]));
    }
    for (long i = g; i < 12800000L; i += stride)
        m2 = fmaxf(m2, amax4(*(const float4*)&emb[i * 4]));
    m3 = amax4(*(const float4*)&h0[g * 4]);
#pragma unroll
    for (int off = 16; off > 0; off >>= 1) {
        m0 = fmaxf(m0, __shfl_xor_sync(0xffffffffu, m0, off));
        m1 = fmaxf(m1, __shfl_xor_sync(0xffffffffu, m1, off));
        m2 = fmaxf(m2, __shfl_xor_sync(0xffffffffu, m2, off));
        m3 = fmaxf(m3, __shfl_xor_sync(0xffffffffu, m3, off));
    }
    if ((threadIdx.x & 31) == 0) {
        atomicMax(&d_absmax[0], __float_as_uint(m0));
        atomicMax(&d_absmax[1], __float_as_uint(m1));
        atomicMax(&d_absmax[2], __float_as_uint(m2));
        atomicMax(&d_absmax[3], __float_as_uint(m3));
    }
}

// ------------------------- init: quantize weights/emb/h0, layout c0 -------------------------
__global__ void init_quant(const float* __restrict__ Wih, const float* __restrict__ Whh,
                           const float* __restrict__ emb,
                           const float* __restrict__ h0,  const float* __restrict__ c0)
{
    int idx = blockIdx.x * 256 + threadIdx.x;
    float iWih = QMAXF / fmaxf(__uint_as_float(d_absmax[0]), 1e-20f);
    float iWhh = QMAXF / fmaxf(__uint_as_float(d_absmax[1]), 1e-20f);
    float iEmb = QMAXF / fmaxf(__uint_as_float(d_absmax[2]), 1e-20f);
    float iH0  = QMAXF / fmaxf(__uint_as_float(d_absmax[3]), 1e-20f);

    if (idx < 1048576) {
        quant16x4(*(const float4*)&Wih[idx * 4], iWih,
                  (char4*)&d_Wihq1[idx * 4], (char4*)&d_Wihq0[idx * 4]);
        quant16x4(*(const float4*)&Whh[idx * 4], iWhh,
                  (char4*)&d_Whhq1[idx * 4], (char4*)&d_Whhq0[idx * 4]);
    }
    for (long i = idx; i < 12800000L; i += 4194304L)
        quant16x4(*(const float4*)&emb[i * 4], iEmb,
                  (char4*)&d_embq1[i * 4], (char4*)&d_embq0[i * 4]);
    if (idx < 262144)
        quant16x4(*(const float4*)&h0[idx * 4], iH0,
                  (char4*)&d_hq1[0][idx * 4], (char4*)&d_hq0[0][idx * 4]);
    if (idx < 1048576) {
        // c0 -> fragment layout (16-warp geometry)
        int b = idx >> 10, hc = idx & 1023;
        int bm = b >> 7, rb = b & 127;
        int wm = rb >> 5, mf = (rb >> 4) & 1, rr = (rb >> 3) & 1, g = rb & 7;
        int bn = hc >> 5, hcl = hc & 31;
        int wn = hcl >> 3, tg = (hcl & 7) >> 1, e = hcl & 1;
        int warp = wn * 4 + wm, lane = g * 4 + tg, q = rr * 2 + e;
        int ci = (((bm * 32 + bn) * 16 + warp) * 2 + mf) * 128 + lane * 4 + q;
        d_Cfrag[ci] = c0[idx];
    }
    if (idx < 131072) d_logits[idx] = 0.0f;
}

// ------------------------- input GEMM: Xg = emb[x] @ W_ih^T + (b_ih + b_hh) -------------------------
__global__ void __launch_bounds__(512, 1) input_gemm(const int* __restrict__ x,
                                                     const float* __restrict__ b_ih,
                                                     const float* __restrict__ b_hh)
{
    extern __shared__ char smem[];
    uint32_t sb = smem_u32(smem);
    int tid = threadIdx.x;
    int bn = blockIdx.x, bm = blockIdx.y;
    int warp = tid >> 5, lane = tid & 31;
    int wm = warp & 3, wn = warp >> 2;
    int g = lane >> 2, tg = lane & 3;
    int hc0 = bn * 32;

    float sAB = (__uint_as_float(d_absmax[2]) / QMAXF) * (__uint_as_float(d_absmax[0]) / QMAXF);
    float sHIc = sAB * 65536.0f, sLOc = sAB * 256.0f;

    int* toks = (int*)(smem + 512);
    if (tid < 128) {
        int row = bm * 128 + tid;          // row = t*B + b
        toks[tid] = x[(row & 1023) * 64 + (row >> 10)];
    }
    __syncthreads();

    int r = tid >> 2, c = tid & 3;
    uint32_t offA = (uint32_t)(r * 80 + c * 16);
    size_t aoff = (size_t)toks[r] * 1024 + c * 16;
    size_t boff = (size_t)n_of(r, hc0) * 1024 + c * 16;

    uint32_t laneA = (uint32_t)((wm * 32 + (lane & 15)) * 80 + (lane >> 4) * 16);
    uint32_t laneB = (uint32_t)((wn * 32 + ((lane >> 4) << 3) + (lane & 7)) * 80
                                + ((lane >> 3) & 1) * 16);

    int acc1[2][4][4], acc2[2][4][4];
#pragma unroll
    for (int i = 0; i < 2; i++)
#pragma unroll
        for (int j = 0; j < 4; j++)
#pragma unroll
            for (int q = 0; q < 4; q++) { acc1[i][j][q] = 0; acc2[i][j][q] = 0; }

    {
        uint32_t st = sb + CTRL;
        CP16(st +         offA, d_embq1 + aoff);
        CP16(st + 10240 + offA, d_embq0 + aoff);
        CP16(st + 20480 + offA, d_Wihq1 + boff);
        CP16(st + 30720 + offA, d_Wihq0 + boff);
    }
    CP_COMMIT();

    for (int kt = 0; kt < 16; kt++) {
        if (kt + 1 < 16) {
            int k0 = (kt + 1) * 64;
            uint32_t st = sb + CTRL + ((kt + 1) & 1) * STAGE;
            CP16(st +         offA, d_embq1 + aoff + k0);
            CP16(st + 10240 + offA, d_embq0 + aoff + k0);
            CP16(st + 20480 + offA, d_Wihq1 + boff + k0);
            CP16(st + 30720 + offA, d_Wihq0 + boff + k0);
        }
        CP_COMMIT();
        CP_WAIT1();
        __syncthreads();
        uint32_t s0 = sb + CTRL + (kt & 1) * STAGE;
        gemm_chunk_i8(acc1, acc2, s0 + laneA, s0 + 10240 + laneA,
                                  s0 + 20480 + laneB, s0 + 30720 + laneB);
        __syncthreads();
    }

    // epilogue: combine terms, add biases, store in fragment order
#pragma unroll
    for (int mf = 0; mf < 2; mf++)
#pragma unroll
        for (int nf = 0; nf < 4; nf++) {
            int n0 = nf * 1024 + hc0 + wn * 8 + 2 * tg;
            float be0 = b_ih[n0] + b_hh[n0];
            float be1 = b_ih[n0 + 1] + b_hh[n0 + 1];
            size_t off = ((((size_t)bm * 32 + bn) * 16 + warp) * 8 + mf * 4 + nf) * 128 + lane * 4;
            float4 v;
            v.x = sHIc * (float)acc1[mf][nf][0] + sLOc * (float)acc2[mf][nf][0] + be0;
            v.y = sHIc * (float)acc1[mf][nf][1] + sLOc * (float)acc2[mf][nf][1] + be1;
            v.z = sHIc * (float)acc1[mf][nf][2] + sLOc * (float)acc2[mf][nf][2] + be0;
            v.w = sHIc * (float)acc1[mf][nf][3] + sLOc * (float)acc2[mf][nf][3] + be1;
            *(float4*)&d_Xg[off] = v;
        }
}

// ------------------------- one recurrent step -------------------------
__global__ void __launch_bounds__(512, 1) step_kernel(int t,
                                                      const float* __restrict__ Wout,
                                                      const float* __restrict__ b_out,
                                                      float* __restrict__ out)
{
    extern __shared__ char smem[];
    uint32_t sb = smem_u32(smem);
    int tid = threadIdx.x;
    int bn = blockIdx.x, bm = blockIdx.y;
    int warp = tid >> 5, lane = tid & 31;
    int wm = warp & 3, wn = warp >> 2;
    int g = lane >> 2, tg = lane & 3;
    int m0 = bm * 128, hc0 = bn * 32;

    if (t > 0 && bn == 0 && bm == 0) {
        int tb = (t - 1) << 11;
        for (int i = tid; i < 1024; i += 512) {
            float l0 = d_logits[tb + i * 2 + 0] + b_out[0];
            float l1 = d_logits[tb + i * 2 + 1] + b_out[1];
            float mx = fmaxf(l0, l1);
            float lse = mx + logf(expf(l0 - mx) + expf(l1 - mx));
            out[tb + i * 2 + 0] = l0 - lse;
            out[tb + i * 2 + 1] = l1 - lse;
        }
    }

    float sh  = (t == 0) ? (__uint_as_float(d_absmax[3]) / QMAXF) : (1.0f / QMAXF);
    float sAB = sh * (__uint_as_float(d_absmax[1]) / QMAXF);
    float sHIc = sAB * 65536.0f, sLOc = sAB * 256.0f;

    const signed char* hQ1 = d_hq1[t & 1];
    const signed char* hQ0 = d_hq0[t & 1];
    signed char* nQ1 = d_hq1[(t + 1) & 1];
    signed char* nQ0 = d_hq0[(t + 1) & 1];

    float* ws = (float*)smem;   // 64 floats: [cls][hcL 0..31]
    if (tid < 64) ws[tid] = Wout[(tid >> 5) * 1024 + hc0 + (tid & 31)];
    __syncthreads();

    int r = tid >> 2, c = tid & 3;
    uint32_t offA = (uint32_t)(r * 80 + c * 16);
    size_t aoff = (size_t)(m0 + r) * 1024 + c * 16;
    size_t boff = (size_t)n_of(r, hc0) * 1024 + c * 16;

    uint32_t laneA = (uint32_t)((wm * 32 + (lane & 15)) * 80 + (lane >> 4) * 16);
    uint32_t laneB = (uint32_t)((wn * 32 + ((lane >> 4) << 3) + (lane & 7)) * 80
                                + ((lane >> 3) & 1) * 16);

    int acc1[2][4][4], acc2[2][4][4];
#pragma unroll
    for (int i = 0; i < 2; i++)
#pragma unroll
        for (int j = 0; j < 4; j++)
#pragma unroll
            for (int q = 0; q < 4; q++) { acc1[i][j][q] = 0; acc2[i][j][q] = 0; }

    {
        uint32_t st = sb + CTRL;
        CP16(st +         offA, hQ1 + aoff);
        CP16(st + 10240 + offA, hQ0 + aoff);
        CP16(st + 20480 + offA, d_Whhq1 + boff);
        CP16(st + 30720 + offA, d_Whhq0 + boff);
    }
    CP_COMMIT();

    for (int kt = 0; kt < 16; kt++) {
        if (kt + 1 < 16) {
            int k0 = (kt + 1) * 64;
            uint32_t st = sb + CTRL + ((kt + 1) & 1) * STAGE;
            CP16(st +         offA, hQ1 + aoff + k0);
            CP16(st + 10240 + offA, hQ0 + aoff + k0);
            CP16(st + 20480 + offA, d_Whhq1 + boff + k0);
            CP16(st + 30720 + offA, d_Whhq0 + boff + k0);
        }
        CP_COMMIT();
        CP_WAIT1();
        __syncthreads();
        uint32_t s0 = sb + CTRL + (kt & 1) * STAGE;
        gemm_chunk_i8(acc1, acc2, s0 + laneA, s0 + 10240 + laneA,
                                  s0 + 20480 + laneB, s0 + 30720 + laneB);
        __syncthreads();
    }

    // ---------------- fused LSTM epilogue ----------------
    size_t xgbase = ((((size_t)(t * 8 + bm) * 32 + bn) * 16 + warp) * 8) * 128 + lane * 4;
    size_t cbase  = ((((size_t)bm * 32 + bn) * 16 + warp) * 2) * 128 + lane * 4;

    float lsum[2][2][2];
#pragma unroll
    for (int i = 0; i < 2; i++)
#pragma unroll
        for (int j = 0; j < 2; j++) { lsum[i][j][0] = 0.0f; lsum[i][j][1] = 0.0f; }

#pragma unroll
    for (int mf = 0; mf < 2; mf++) {
        float4 CPc = *(const float4*)&d_Cfrag[cbase + mf * 128];
        float cprev[4] = {CPc.x, CPc.y, CPc.z, CPc.w};
        float4 PI = *(const float4*)&d_Xg[xgbase + (size_t)(mf * 4 + 0) * 128];
        float4 PF = *(const float4*)&d_Xg[xgbase + (size_t)(mf * 4 + 1) * 128];
        float4 PG = *(const float4*)&d_Xg[xgbase + (size_t)(mf * 4 + 2) * 128];
        float4 PO = *(const float4*)&d_Xg[xgbase + (size_t)(mf * 4 + 3) * 128];
        float pri[4] = {PI.x, PI.y, PI.z, PI.w};
        float prf[4] = {PF.x, PF.y, PF.z, PF.w};
        float prg[4] = {PG.x, PG.y, PG.z, PG.w};
        float pro[4] = {PO.x, PO.y, PO.z, PO.w};
        float cnew[4];
#pragma unroll
        for (int q = 0; q < 4; q++) {
            int rr = q >> 1, e = q & 1;
            float I = sHIc * (float)acc1[mf][0][q] + sLOc * (float)acc2[mf][0][q] + pri[q];
            float F = sHIc * (float)acc1[mf][1][q] + sLOc * (float)acc2[mf][1][q] + prf[q];
            float G = sHIc * (float)acc1[mf][2][q] + sLOc * (float)acc2[mf][2][q] + prg[q];
            float O = sHIc * (float)acc1[mf][3][q] + sLOc * (float)acc2[mf][3][q] + pro[q];
            float si = 1.0f / (1.0f + expf(-I));
            float sf = 1.0f / (1.0f + expf(-F));
            float so = 1.0f / (1.0f + expf(-O));
            float c2 = sf * cprev[q] + si * tanhf(G);
            float h2 = so * tanhf(c2);
            cnew[q] = c2;
            int b  = m0 + wm * 32 + mf * 16 + rr * 8 + g;
            int hcL = wn * 8 + 2 * tg + e;
            int hc = hc0 + hcL;
            int qh = __float2int_rn(h2 * QMAXF);
            int qh1 = (qh + 128) >> 8;
            nQ1[b * 1024 + hc] = (signed char)qh1;
            nQ0[b * 1024 + hc] = (signed char)(qh - (qh1 << 8));
            lsum[mf][rr][0] += c2 * ws[hcL];
            lsum[mf][rr][1] += c2 * ws[32 + hcL];
        }
        *(float4*)&d_Cfrag[cbase + mf * 128] = make_float4(cnew[0], cnew[1], cnew[2], cnew[3]);
    }

#pragma unroll
    for (int mf = 0; mf < 2; mf++)
#pragma unroll
        for (int rr = 0; rr < 2; rr++)
#pragma unroll
            for (int cls = 0; cls < 2; cls++) {
                float v = lsum[mf][rr][cls];
                v += __shfl_xor_sync(0xffffffffu, v, 1);
                v += __shfl_xor_sync(0xffffffffu, v, 2);
                if (tg == 0) {
                    int b = m0 + wm * 32 + mf * 16 + rr * 8 + g;
                    atomicAdd(&d_logits[(t << 11) + b * 2 + cls], v);
                }
            }
}

// ------------------------- finalize t=63 + out_final -------------------------
__global__ void final_kernel(const float* __restrict__ b_out, float* __restrict__ out)
{
    int i = blockIdx.x * 256 + threadIdx.x;
    if (i < 1024) {
        int tb = 63 << 11;
        float l0 = d_logits[tb + i * 2 + 0] + b_out[0];
        float l1 = d_logits[tb + i * 2 + 1] + b_out[1];
        float mx = fmaxf(l0, l1);
        float lse = mx + logf(expf(l0 - mx) + expf(l1 - mx));
        out[tb + i * 2 + 0] = l0 - lse;
        out[tb + i * 2 + 1] = l1 - lse;
        out[131072 + i * 2 + 0] = l0;
        out[131072 + i * 2 + 1] = l1;
    }
}

// ------------------------- launch -------------------------
extern "C" void kernel_launch(void* const* d_in, const int* in_sizes, int n_in,
                              void* d_out, int out_size)
{
    (void)in_sizes; (void)n_in; (void)out_size;
    const int*   x    = (const int*)d_in[0];
    const float* emb  = (const float*)d_in[1];
    const float* Wih  = (const float*)d_in[2];
    const float* Whh  = (const float*)d_in[3];
    const float* bih  = (const float*)d_in[4];
    const float* bhh  = (const float*)d_in[5];
    const float* Wout = (const float*)d_in[6];
    const float* bout = (const float*)d_in[7];
    const float* h0   = (const float*)d_in[8];
    const float* c0   = (const float*)d_in[9];
    float* out = (float*)d_out;

    cudaFuncSetAttribute(input_gemm, cudaFuncAttributeMaxDynamicSharedMemorySize, SMEM_BYTES);
    cudaFuncSetAttribute(step_kernel, cudaFuncAttributeMaxDynamicSharedMemorySize, SMEM_BYTES);

    zero_absmax<<<1, 32>>>();
    absmax_kernel<<<1024, 256>>>(Wih, Whh, emb, h0);
    init_quant<<<16384, 256>>>(Wih, Whh, emb, h0, c0);
    input_gemm<<<dim3(32, 512), 512, SMEM_BYTES>>>(x, bih, bhh);
    for (int t = 0; t < 64; t++)
        step_kernel<<<dim3(32, 8), 512, SMEM_BYTES>>>(t, Wout, bout, out);
    final_kernel<<<4, 256>>>(bout, out);
}